// round 10
// baseline (speedup 1.0000x reference)
#include <cuda_runtime.h>
#include <cuda_fp16.h>
#include <cstdint>

// Problem constants
#define BZ 4
#define SEQ 2048
#define DM 1024
#define NH 16
#define HD 64
#define M_TOT 8192
#define N_TOT 3072

// Scratch (fp16)
__device__ __half g_Qh[BZ*NH*SEQ*HD];
__device__ __half g_Kh[BZ*NH*SEQ*HD];
__device__ __half g_Vh[BZ*NH*SEQ*HD];
__device__ __half g_Xh[M_TOT*DM];
__device__ __half g_Wt[(size_t)N_TOT*DM];   // W transposed [n][k]

// ---------------------------------------------------------------------------
// helpers
// ---------------------------------------------------------------------------
__device__ __forceinline__ void mma16(float* c, const uint32_t* a, uint32_t b0, uint32_t b1){
    asm volatile("mma.sync.aligned.m16n8k16.row.col.f32.f16.f16.f32 "
        "{%0,%1,%2,%3}, {%4,%5,%6,%7}, {%8,%9}, {%0,%1,%2,%3};"
        : "+f"(c[0]), "+f"(c[1]), "+f"(c[2]), "+f"(c[3])
        : "r"(a[0]), "r"(a[1]), "r"(a[2]), "r"(a[3]), "r"(b0), "r"(b1));
}
__device__ __forceinline__ void ldsm4(uint32_t* r, uint32_t addr){
    asm volatile("ldmatrix.sync.aligned.m8n8.x4.shared.b16 {%0,%1,%2,%3}, [%4];"
        : "=r"(r[0]), "=r"(r[1]), "=r"(r[2]), "=r"(r[3]) : "r"(addr));
}
__device__ __forceinline__ void ldsm4t(uint32_t* r, uint32_t addr){
    asm volatile("ldmatrix.sync.aligned.m8n8.x4.trans.shared.b16 {%0,%1,%2,%3}, [%4];"
        : "=r"(r[0]), "=r"(r[1]), "=r"(r[2]), "=r"(r[3]) : "r"(addr));
}
__device__ __forceinline__ uint32_t pack2(float lo, float hi){
    uint32_t r; asm("cvt.rn.f16x2.f32 %0, %1, %2;" : "=r"(r) : "f"(hi), "f"(lo)); return r;
}
__device__ __forceinline__ uint32_t smem_u32(const void* p){
    uint32_t a;
    asm("{ .reg .u64 t; cvta.to.shared.u64 t, %1; cvt.u32.u64 %0, t; }" : "=r"(a) : "l"(p));
    return a;
}
__device__ __forceinline__ void cp16(uint32_t dst, const void* src){
    asm volatile("cp.async.cg.shared.global [%0], [%1], 16;" :: "r"(dst), "l"(src));
}
#define CP_COMMIT() asm volatile("cp.async.commit_group;" ::: "memory")
#define CP_WAIT(n)  asm volatile("cp.async.wait_group %0;" :: "n"(n) : "memory")

// ---------------------------------------------------------------------------
// Prepass
// ---------------------------------------------------------------------------
__global__ __launch_bounds__(256) void cvt_x(const float* __restrict__ x)
{
    const size_t n4 = (size_t)M_TOT * DM / 4;
    const size_t gid = (size_t)blockIdx.x * blockDim.x + threadIdx.x;
    const size_t stride = (size_t)gridDim.x * blockDim.x;
    for (size_t i = gid * 4; i < n4; i += stride * 4) {
        float4 v0 = ((const float4*)x)[i];
        float4 v1 = ((const float4*)x)[i + 1];
        float4 v2 = ((const float4*)x)[i + 2];
        float4 v3 = ((const float4*)x)[i + 3];
        __half2* o = (__half2*)(g_Xh + i * 4);
        o[0] = __floats2half2_rn(v0.x, v0.y); o[1] = __floats2half2_rn(v0.z, v0.w);
        o[2] = __floats2half2_rn(v1.x, v1.y); o[3] = __floats2half2_rn(v1.z, v1.w);
        o[4] = __floats2half2_rn(v2.x, v2.y); o[5] = __floats2half2_rn(v2.z, v2.w);
        o[6] = __floats2half2_rn(v3.x, v3.y); o[7] = __floats2half2_rn(v3.z, v3.w);
    }
}
__global__ __launch_bounds__(256) void cvt_w(const float* __restrict__ W)
{
    __shared__ float tile[32][33];
    const int n0 = blockIdx.x * 32, k0 = blockIdx.y * 32;
    const int tx = threadIdx.x & 31, ty = threadIdx.x >> 5;
    #pragma unroll
    for (int j = 0; j < 4; j++)
        tile[ty + 8 * j][tx] = W[(size_t)(k0 + ty + 8 * j) * N_TOT + n0 + tx];
    __syncthreads();
    #pragma unroll
    for (int j = 0; j < 4; j++)
        g_Wt[(size_t)(n0 + ty + 8 * j) * DM + k0 + tx] = __float2half_rn(tile[tx][ty + 8 * j]);
}

// ---------------------------------------------------------------------------
// Kernel 1: QKV GEMM, fp16 mma + ldmatrix + 4-stage cp.async, 512 threads.
// CTA tile 256x128, BK=32, 16 warps as 4M x 4N, warp tile 64x32.
// ---------------------------------------------------------------------------
#define ASTR 40
#define BSTR 40
#define SA_H (256*ASTR)
#define SB_H (128*BSTR)
#define SA_B (SA_H*2)
#define SB_B (SB_H*2)
#define NKB  (DM/32)
#define NSTG 4

__global__ __launch_bounds__(512, 1) void qkv_gemm(const float* __restrict__ bias)
{
    extern __shared__ __half smh[];
    __half* sA = smh;
    __half* sB = smh + NSTG * SA_H;
    const uint32_t uA = smem_u32(sA);
    const uint32_t uB = smem_u32(sB);

    const int tid  = threadIdx.x;
    const int wid  = tid >> 5;
    const int lane = tid & 31;
    const int g = lane >> 2, t = lane & 3;
    const int wrow = wid & 3;      // m offset = wrow*64
    const int wcol = wid >> 2;     // n offset = wcol*32
    const int bm = blockIdx.y, bn = blockIdx.x;

    const __half* Ab = g_Xh + (size_t)(bm * 256) * DM;
    const __half* Bb = g_Wt + (size_t)(bn * 128) * DM;

    // A: 1024 chunks, 2/thread; B: 512 chunks, 1/thread
    int arow[2], acol[2];
    #pragma unroll
    for (int l = 0; l < 2; l++) {
        int idx = tid + l * 512;
        arow[l] = idx >> 2;
        acol[l] = (idx & 3) * 8;
    }
    const int brow = tid >> 2;
    const int bcol = (tid & 3) * 8;

    auto issue = [&](int slot, int k0) {
        uint32_t pa = uA + slot * SA_B;
        uint32_t pb = uB + slot * SB_B;
        #pragma unroll
        for (int l = 0; l < 2; l++)
            cp16(pa + (arow[l] * ASTR + acol[l]) * 2, Ab + (size_t)arow[l] * DM + k0 + acol[l]);
        cp16(pb + (brow * BSTR + bcol) * 2, Bb + (size_t)brow * DM + k0 + bcol);
    };

    float acc[4][4][4];
    #pragma unroll
    for (int mt = 0; mt < 4; mt++)
        #pragma unroll
        for (int nt = 0; nt < 4; nt++)
            #pragma unroll
            for (int e = 0; e < 4; e++) acc[mt][nt][e] = 0.f;

    issue(0, 0);  CP_COMMIT();
    issue(1, 32); CP_COMMIT();
    issue(2, 64); CP_COMMIT();
    CP_WAIT(2);
    __syncthreads();

    const uint32_t aBase = uA + (wrow * 64 + (lane & 15)) * (ASTR * 2) + ((lane & 16) ? 16 : 0);
    const uint32_t bBase = uB + (wcol * 32 + (lane & 7) + ((lane & 16) ? 8 : 0)) * (BSTR * 2)
                         + ((lane & 8) ? 16 : 0);

    int slot = 0;
    #pragma unroll 1
    for (int kb = 0; kb < NKB; kb++) {
        uint32_t af[2][4][4], bf[2][2][4];
        #pragma unroll
        for (int kt = 0; kt < 2; kt++) {
            #pragma unroll
            for (int mt = 0; mt < 4; mt++)
                ldsm4(af[kt][mt], aBase + slot * SA_B + mt * 16 * (ASTR * 2) + kt * 32);
            #pragma unroll
            for (int ntp = 0; ntp < 2; ntp++)
                ldsm4(bf[kt][ntp], bBase + slot * SB_B + ntp * 16 * (BSTR * 2) + kt * 32);
        }

        if (kb + 3 < NKB) {
            int ns = slot + 3; if (ns >= NSTG) ns -= NSTG;
            issue(ns, (kb + 3) * 32);
            CP_COMMIT();
        }

        #pragma unroll
        for (int kt = 0; kt < 2; kt++)
            #pragma unroll
            for (int mt = 0; mt < 4; mt++)
                #pragma unroll
                for (int nt = 0; nt < 4; nt++)
                    mma16(acc[mt][nt], af[kt][mt],
                          bf[kt][nt >> 1][(nt & 1) * 2], bf[kt][nt >> 1][(nt & 1) * 2 + 1]);

        if (kb + 3 < NKB)      { CP_WAIT(2); }
        else if (kb + 2 < NKB) { CP_WAIT(1); }
        else if (kb + 1 < NKB) { CP_WAIT(0); }
        __syncthreads();
        if (++slot == NSTG) slot = 0;
    }

    // Epilogue
    #pragma unroll
    for (int nt = 0; nt < 4; nt++) {
        int n0 = bn * 128 + wcol * 32 + nt * 8 + 2 * t;
        float bx = __ldg(&bias[n0]), by = __ldg(&bias[n0 + 1]);
        int h = n0 / 192;
        int r = n0 - h * 192;
        __half* dst = (r < 64) ? g_Qh : ((r < 128) ? g_Kh : g_Vh);
        float scl = (r < 64) ? 0.125f : 1.f;
        #pragma unroll
        for (int mt = 0; mt < 4; mt++) {
            #pragma unroll
            for (int half_ = 0; half_ < 2; half_++) {
                int m  = bm * 256 + wrow * 64 + mt * 16 + g + half_ * 8;
                int b_ = m >> 11;
                int s_ = m & 2047;
                size_t o = ((((size_t)b_ * NH + h) * SEQ) + s_) * HD + (r & 63);
                *(__half2*)(dst + o) = __floats2half2_rn((acc[mt][nt][half_ * 2]     + bx) * scl,
                                                         (acc[mt][nt][half_ * 2 + 1] + by) * scl);
            }
        }
    }
}

// ---------------------------------------------------------------------------
// Kernel 2: causal flash attention, fp16 mma + ldmatrix, 512 threads.
// 16 warps x 16 q-rows = 256 q-rows/CTA; KV tiles 64 keys, cp.async dbl-buffer.
// ---------------------------------------------------------------------------
#define QSTR 72
#define KSTR 72
#define KV_B (64*KSTR*2)
#define CTAQ 256
#define L2E 1.44269504f

__global__ __launch_bounds__(512, 1) void attn_fa(float* __restrict__ out)
{
    extern __shared__ __half smh[];
    __half* Qs = smh;
    __half* Ks = Qs + CTAQ * QSTR;
    __half* Vs = Ks + 2 * 64 * KSTR;
    const uint32_t uQ = smem_u32(Qs);
    const uint32_t uK = smem_u32(Ks);
    const uint32_t uV = smem_u32(Vs);

    const int tid  = threadIdx.x;
    const int wid  = tid >> 5;
    const int lane = tid & 31;
    const int g = lane >> 2, t = lane & 3;
    const int qt = gridDim.x - 1 - blockIdx.x;
    const int h = blockIdx.y, b = blockIdx.z;
    const int wb = wid * 16;                  // warp q-row base (16 rows/warp)
    const int qbase = qt * CTAQ;
    const int row0 = qbase + wb + g;

    const size_t hb = (((size_t)b * NH + h) * SEQ) * HD;
    const int nkb = (qt + 1) * (CTAQ / 64);

    // K/V: 512 chunks per tensor -> 1/thread. Q: 2048 chunks -> 4/thread.
    const int kvrow = tid >> 3;
    const int kvcol = (tid & 7) * 8;
    auto issueKV = [&](int kb, int slot) {
        const __half* ks = g_Kh + hb + (size_t)kb * 64 * HD;
        const __half* vs = g_Vh + hb + (size_t)kb * 64 * HD;
        cp16(uK + slot * KV_B + (kvrow * KSTR + kvcol) * 2, ks + kvrow * HD + kvcol);
        cp16(uV + slot * KV_B + (kvrow * KSTR + kvcol) * 2, vs + kvrow * HD + kvcol);
    };

    issueKV(0, 0);
    CP_COMMIT();
    {
        const __half* qs = g_Qh + hb + (size_t)qbase * HD;
        #pragma unroll
        for (int i = 0; i < 4; i++) {
            int idx = tid + i * 512;
            int r = idx >> 3, c = (idx & 7) * 8;
            cp16(uQ + (r * QSTR + c) * 2, qs + r * HD + c);
        }
    }
    CP_COMMIT();
    CP_WAIT(0);
    __syncthreads();

    // Q fragments: [kt][4]
    uint32_t aq[4][4];
    {
        const uint32_t qb = uQ + (wb + (lane & 15)) * (QSTR * 2) + ((lane & 16) ? 16 : 0);
        #pragma unroll
        for (int kt = 0; kt < 4; kt++)
            ldsm4(aq[kt], qb + kt * 32);
    }

    float o[8][4];
    #pragma unroll
    for (int nt = 0; nt < 8; nt++)
        #pragma unroll
        for (int e = 0; e < 4; e++) o[nt][e] = 0.f;
    float m0 = -1e30f, m1 = -1e30f, l0 = 0.f, l1 = 0.f;

    const uint32_t kfOff = ((lane & 7) + ((lane & 16) ? 8 : 0)) * (KSTR * 2) + ((lane & 8) ? 16 : 0);
    const uint32_t vfOff = ((lane & 7) + ((lane & 8) ? 8 : 0)) * (KSTR * 2) + ((lane & 16) ? 16 : 0);

    #pragma unroll 1
    for (int kb = 0; kb < nkb; kb++) {
        const int slot = kb & 1;
        if (kb + 1 < nkb) { issueKV(kb + 1, slot ^ 1); CP_COMMIT(); }
        if (kb + 1 < nkb) { CP_WAIT(1); } else { CP_WAIT(0); }
        __syncthreads();

        if (kb * 64 <= qbase + wb + 15) {
            // ---- QK^T ----
            float s[8][4];
            #pragma unroll
            for (int nt = 0; nt < 8; nt++)
                #pragma unroll
                for (int e = 0; e < 4; e++) s[nt][e] = 0.f;

            const uint32_t kbase_ = uK + slot * KV_B + kfOff;
            #pragma unroll
            for (int kt = 0; kt < 4; kt++) {
                uint32_t kf[4][4];
                #pragma unroll
                for (int ntp = 0; ntp < 4; ntp++)
                    ldsm4(kf[ntp], kbase_ + ntp * 16 * (KSTR * 2) + kt * 32);
                #pragma unroll
                for (int nt = 0; nt < 8; nt++)
                    mma16(s[nt], aq[kt], kf[nt >> 1][(nt & 1) * 2], kf[nt >> 1][(nt & 1) * 2 + 1]);
            }

            // causal mask near diagonal
            if (kb * 64 + 63 > qbase + wb) {
                #pragma unroll
                for (int nt = 0; nt < 8; nt++) {
                    int col = kb * 64 + nt * 8 + 2 * t;
                    if (col     > row0)     s[nt][0] = -1e30f;
                    if (col + 1 > row0)     s[nt][1] = -1e30f;
                    if (col     > row0 + 8) s[nt][2] = -1e30f;
                    if (col + 1 > row0 + 8) s[nt][3] = -1e30f;
                }
            }

            // ---- online softmax ----
            float b0m = -1e30f, b1m = -1e30f;
            #pragma unroll
            for (int nt = 0; nt < 8; nt++) {
                b0m = fmaxf(b0m, fmaxf(s[nt][0], s[nt][1]));
                b1m = fmaxf(b1m, fmaxf(s[nt][2], s[nt][3]));
            }
            #pragma unroll
            for (int d = 1; d <= 2; d <<= 1) {
                b0m = fmaxf(b0m, __shfl_xor_sync(0xffffffffu, b0m, d));
                b1m = fmaxf(b1m, __shfl_xor_sync(0xffffffffu, b1m, d));
            }
            float n0 = fmaxf(m0, b0m), n1 = fmaxf(m1, b1m);
            float c0 = exp2f((m0 - n0) * L2E), c1 = exp2f((m1 - n1) * L2E);

            uint32_t pc[8][2];
            float s0 = 0.f, s1 = 0.f;
            #pragma unroll
            for (int nt = 0; nt < 8; nt++) {
                float p0 = exp2f((s[nt][0] - n0) * L2E);
                float p1 = exp2f((s[nt][1] - n0) * L2E);
                float p2 = exp2f((s[nt][2] - n1) * L2E);
                float p3 = exp2f((s[nt][3] - n1) * L2E);
                s0 += p0 + p1; s1 += p2 + p3;
                pc[nt][0] = pack2(p0, p1);
                pc[nt][1] = pack2(p2, p3);
            }
            #pragma unroll
            for (int d = 1; d <= 2; d <<= 1) {
                s0 += __shfl_xor_sync(0xffffffffu, s0, d);
                s1 += __shfl_xor_sync(0xffffffffu, s1, d);
            }
            l0 = l0 * c0 + s0;
            l1 = l1 * c1 + s1;
            m0 = n0; m1 = n1;

            #pragma unroll
            for (int nt = 0; nt < 8; nt++) {
                o[nt][0] *= c0; o[nt][1] *= c0;
                o[nt][2] *= c1; o[nt][3] *= c1;
            }

            // ---- PV (P in registers) ----
            const uint32_t vbase_ = uV + slot * KV_B + vfOff;
            #pragma unroll
            for (int kt = 0; kt < 4; kt++) {
                uint32_t vf[4][4];
                #pragma unroll
                for (int ntp = 0; ntp < 4; ntp++)
                    ldsm4t(vf[ntp], vbase_ + kt * 16 * (KSTR * 2) + ntp * 32);
                uint32_t ap[4] = {pc[2*kt][0], pc[2*kt][1], pc[2*kt+1][0], pc[2*kt+1][1]};
                #pragma unroll
                for (int nt = 0; nt < 8; nt++)
                    mma16(o[nt], ap, vf[nt >> 1][(nt & 1) * 2], vf[nt >> 1][(nt & 1) * 2 + 1]);
            }
        }

        __syncthreads();
    }

    // ---- write out ----
    const float i0 = 1.f / l0, i1 = 1.f / l1;
    float* w0 = out + ((size_t)b * SEQ + row0) * DM + h * HD + 2 * t;
    float* w1 = out + ((size_t)b * SEQ + row0 + 8) * DM + h * HD + 2 * t;
    #pragma unroll
    for (int nt = 0; nt < 8; nt++) {
        *(float2*)(w0 + nt * 8) = make_float2(o[nt][0] * i0, o[nt][1] * i0);
        *(float2*)(w1 + nt * 8) = make_float2(o[nt][2] * i1, o[nt][3] * i1);
    }
}

// ---------------------------------------------------------------------------
extern "C" void kernel_launch(void* const* d_in, const int* in_sizes, int n_in,
                              void* d_out, int out_size)
{
    (void)in_sizes; (void)n_in; (void)out_size;
    const float* x    = (const float*)d_in[0];
    const float* Wqkv = (const float*)d_in[1];
    const float* bqkv = (const float*)d_in[2];
    float* out = (float*)d_out;

    cvt_x<<<592, 256>>>(x);
    cvt_w<<<dim3(N_TOT / 32, DM / 32), 256>>>(Wqkv);

    const int gemm_smem = NSTG * (SA_B + SB_B);              // 122880 B
    cudaFuncSetAttribute(qkv_gemm, cudaFuncAttributeMaxDynamicSharedMemorySize, gemm_smem);
    dim3 ggrid(N_TOT / 128, M_TOT / 256);                    // (24, 32)
    qkv_gemm<<<ggrid, 512, gemm_smem>>>(bqkv);

    const int attn_smem = (CTAQ * QSTR + 4 * 64 * KSTR) * 2; // 73728 B
    cudaFuncSetAttribute(attn_fa, cudaFuncAttributeMaxDynamicSharedMemorySize, attn_smem);
    dim3 agrid(SEQ / CTAQ, NH, BZ);                          // (8, 16, 4)
    attn_fa<<<agrid, 512, attn_smem>>>(out);
}

// round 11
// speedup vs baseline: 1.0908x; 1.0908x over previous
#include <cuda_runtime.h>
#include <cuda_fp16.h>
#include <cstdint>

// Problem constants
#define BZ 4
#define SEQ 2048
#define DM 1024
#define NH 16
#define HD 64
#define M_TOT 8192
#define N_TOT 3072

// Scratch (fp16)
__device__ __half g_Qh[BZ*NH*SEQ*HD];
__device__ __half g_Kh[BZ*NH*SEQ*HD];
__device__ __half g_Vh[BZ*NH*SEQ*HD];
__device__ __half g_Xh[M_TOT*DM];
__device__ __half g_Wt[(size_t)N_TOT*DM];   // W transposed [n][k]

// ---------------------------------------------------------------------------
// helpers
// ---------------------------------------------------------------------------
__device__ __forceinline__ void mma16(float* c, const uint32_t* a, uint32_t b0, uint32_t b1){
    asm volatile("mma.sync.aligned.m16n8k16.row.col.f32.f16.f16.f32 "
        "{%0,%1,%2,%3}, {%4,%5,%6,%7}, {%8,%9}, {%0,%1,%2,%3};"
        : "+f"(c[0]), "+f"(c[1]), "+f"(c[2]), "+f"(c[3])
        : "r"(a[0]), "r"(a[1]), "r"(a[2]), "r"(a[3]), "r"(b0), "r"(b1));
}
__device__ __forceinline__ void ldsm4(uint32_t* r, uint32_t addr){
    asm volatile("ldmatrix.sync.aligned.m8n8.x4.shared.b16 {%0,%1,%2,%3}, [%4];"
        : "=r"(r[0]), "=r"(r[1]), "=r"(r[2]), "=r"(r[3]) : "r"(addr));
}
__device__ __forceinline__ void ldsm4t(uint32_t* r, uint32_t addr){
    asm volatile("ldmatrix.sync.aligned.m8n8.x4.trans.shared.b16 {%0,%1,%2,%3}, [%4];"
        : "=r"(r[0]), "=r"(r[1]), "=r"(r[2]), "=r"(r[3]) : "r"(addr));
}
__device__ __forceinline__ uint32_t pack2(float lo, float hi){
    uint32_t r; asm("cvt.rn.f16x2.f32 %0, %1, %2;" : "=r"(r) : "f"(hi), "f"(lo)); return r;
}
__device__ __forceinline__ uint32_t smem_u32(const void* p){
    uint32_t a;
    asm("{ .reg .u64 t; cvta.to.shared.u64 t, %1; cvt.u32.u64 %0, t; }" : "=r"(a) : "l"(p));
    return a;
}
__device__ __forceinline__ void cp16(uint32_t dst, const void* src){
    asm volatile("cp.async.cg.shared.global [%0], [%1], 16;" :: "r"(dst), "l"(src));
}
#define CP_COMMIT() asm volatile("cp.async.commit_group;" ::: "memory")
#define CP_WAIT(n)  asm volatile("cp.async.wait_group %0;" :: "n"(n) : "memory")

// ---------------------------------------------------------------------------
// Prepass (merged): blocks [0, NWB) transpose-convert W; rest convert x.
// ---------------------------------------------------------------------------
#define NWB ((N_TOT/32)*(DM/32))    // 3072 W-tile blocks
#define NXB 592                     // x blocks

__global__ __launch_bounds__(256) void cvt_all(const float* __restrict__ x,
                                               const float* __restrict__ W)
{
    if (blockIdx.x < NWB) {
        __shared__ float tile[32][33];
        const int bw = blockIdx.x;
        const int n0 = (bw % (N_TOT / 32)) * 32;
        const int k0 = (bw / (N_TOT / 32)) * 32;
        const int tx = threadIdx.x & 31, ty = threadIdx.x >> 5;
        #pragma unroll
        for (int j = 0; j < 4; j++)
            tile[ty + 8 * j][tx] = W[(size_t)(k0 + ty + 8 * j) * N_TOT + n0 + tx];
        __syncthreads();
        #pragma unroll
        for (int j = 0; j < 4; j++)
            g_Wt[(size_t)(n0 + ty + 8 * j) * DM + k0 + tx] = __float2half_rn(tile[tx][ty + 8 * j]);
    } else {
        const size_t n4 = (size_t)M_TOT * DM / 4;
        const size_t gid = (size_t)(blockIdx.x - NWB) * blockDim.x + threadIdx.x;
        const size_t stride = (size_t)NXB * blockDim.x;
        for (size_t i = gid * 4; i < n4; i += stride * 4) {
            float4 v0 = ((const float4*)x)[i];
            float4 v1 = ((const float4*)x)[i + 1];
            float4 v2 = ((const float4*)x)[i + 2];
            float4 v3 = ((const float4*)x)[i + 3];
            __half2* o = (__half2*)(g_Xh + i * 4);
            o[0] = __floats2half2_rn(v0.x, v0.y); o[1] = __floats2half2_rn(v0.z, v0.w);
            o[2] = __floats2half2_rn(v1.x, v1.y); o[3] = __floats2half2_rn(v1.z, v1.w);
            o[4] = __floats2half2_rn(v2.x, v2.y); o[5] = __floats2half2_rn(v2.z, v2.w);
            o[6] = __floats2half2_rn(v3.x, v3.y); o[7] = __floats2half2_rn(v3.z, v3.w);
        }
    }
}

// ---------------------------------------------------------------------------
// Kernel 1: QKV GEMM, fp16 mma + ldmatrix, BK=64, 3-stage cp.async.
// CTA tile 256x128, 8 warps (4M x 2N), warp tile 64x64, 256 threads.
// ---------------------------------------------------------------------------
#define ASTR 72                  // halves per row (64 + 8 pad)
#define SA_H (256*ASTR)
#define SB_H (128*ASTR)
#define SA_B (SA_H*2)            // 36864 B
#define SB_B (SB_H*2)            // 18432 B
#define NKB  (DM/64)             // 16
#define NSTG 3

__global__ __launch_bounds__(256, 1) void qkv_gemm(const float* __restrict__ bias)
{
    extern __shared__ __half smh[];
    __half* sA = smh;
    __half* sB = smh + NSTG * SA_H;
    const uint32_t uA = smem_u32(sA);
    const uint32_t uB = smem_u32(sB);

    const int tid  = threadIdx.x;
    const int wid  = tid >> 5;
    const int lane = tid & 31;
    const int g = lane >> 2, t = lane & 3;
    const int wrow = wid & 3;      // m = wrow*64
    const int wcol = wid >> 2;     // n = wcol*64
    const int bm = blockIdx.y, bn = blockIdx.x;

    const __half* Ab = g_Xh + (size_t)(bm * 256) * DM;
    const __half* Bb = g_Wt + (size_t)(bn * 128) * DM;

    // A: 2048 16B-chunks (8/thread); B: 1024 (4/thread); 8 chunks per row of 64
    int arow[8], acol[8];
    #pragma unroll
    for (int l = 0; l < 8; l++) {
        int idx = tid + l * 256;
        arow[l] = idx >> 3;
        acol[l] = (idx & 7) * 8;
    }
    int brow[4], bcol[4];
    #pragma unroll
    for (int l = 0; l < 4; l++) {
        int idx = tid + l * 256;
        brow[l] = idx >> 3;
        bcol[l] = (idx & 7) * 8;
    }

    auto issue = [&](int slot, int k0) {
        uint32_t pa = uA + slot * SA_B;
        uint32_t pb = uB + slot * SB_B;
        #pragma unroll
        for (int l = 0; l < 8; l++)
            cp16(pa + (arow[l] * ASTR + acol[l]) * 2, Ab + (size_t)arow[l] * DM + k0 + acol[l]);
        #pragma unroll
        for (int l = 0; l < 4; l++)
            cp16(pb + (brow[l] * ASTR + bcol[l]) * 2, Bb + (size_t)brow[l] * DM + k0 + bcol[l]);
    };

    float acc[4][8][4];
    #pragma unroll
    for (int mt = 0; mt < 4; mt++)
        #pragma unroll
        for (int nt = 0; nt < 8; nt++)
            #pragma unroll
            for (int e = 0; e < 4; e++) acc[mt][nt][e] = 0.f;

    issue(0, 0);   CP_COMMIT();
    issue(1, 64);  CP_COMMIT();
    CP_WAIT(1);                    // slot 0 ready
    __syncthreads();

    const uint32_t aBase = uA + (wrow * 64 + (lane & 15)) * (ASTR * 2) + ((lane & 16) ? 16 : 0);
    const uint32_t bBase = uB + (wcol * 64 + (lane & 7) + ((lane & 16) ? 8 : 0)) * (ASTR * 2)
                         + ((lane & 8) ? 16 : 0);

    int slot = 0;
    #pragma unroll 1
    for (int kb = 0; kb < NKB; kb++) {
        const uint32_t aS = aBase + slot * SA_B;
        const uint32_t bS = bBase + slot * SB_B;

        // ---- sub-batch 0: kt 0,1 ----
        uint32_t af[2][4][4], bf[2][4][4];
        #pragma unroll
        for (int kt = 0; kt < 2; kt++) {
            #pragma unroll
            for (int mt = 0; mt < 4; mt++)
                ldsm4(af[kt][mt], aS + mt * 16 * (ASTR * 2) + kt * 32);
            #pragma unroll
            for (int ntp = 0; ntp < 4; ntp++)
                ldsm4(bf[kt][ntp], bS + ntp * 16 * (ASTR * 2) + kt * 32);
        }

        if (kb + 2 < NKB) {
            int ns = slot + 2; if (ns >= NSTG) ns -= NSTG;
            issue(ns, (kb + 2) * 64);
            CP_COMMIT();
        }

        #pragma unroll
        for (int kt = 0; kt < 2; kt++)
            #pragma unroll
            for (int mt = 0; mt < 4; mt++)
                #pragma unroll
                for (int nt = 0; nt < 8; nt++)
                    mma16(acc[mt][nt], af[kt][mt],
                          bf[kt][nt >> 1][(nt & 1) * 2], bf[kt][nt >> 1][(nt & 1) * 2 + 1]);

        // ---- sub-batch 1: kt 2,3 ----
        #pragma unroll
        for (int kt = 0; kt < 2; kt++) {
            #pragma unroll
            for (int mt = 0; mt < 4; mt++)
                ldsm4(af[kt][mt], aS + mt * 16 * (ASTR * 2) + (kt + 2) * 32);
            #pragma unroll
            for (int ntp = 0; ntp < 4; ntp++)
                ldsm4(bf[kt][ntp], bS + ntp * 16 * (ASTR * 2) + (kt + 2) * 32);
        }
        #pragma unroll
        for (int kt = 0; kt < 2; kt++)
            #pragma unroll
            for (int mt = 0; mt < 4; mt++)
                #pragma unroll
                for (int nt = 0; nt < 8; nt++)
                    mma16(acc[mt][nt], af[kt][mt],
                          bf[kt][nt >> 1][(nt & 1) * 2], bf[kt][nt >> 1][(nt & 1) * 2 + 1]);

        if (kb + 2 < NKB)      { CP_WAIT(1); }   // next slot arrived
        else if (kb + 1 < NKB) { CP_WAIT(0); }
        __syncthreads();
        if (++slot == NSTG) slot = 0;
    }

    // Epilogue
    #pragma unroll
    for (int nt = 0; nt < 8; nt++) {
        int n0 = bn * 128 + wcol * 64 + nt * 8 + 2 * t;
        float bx = __ldg(&bias[n0]), by = __ldg(&bias[n0 + 1]);
        int h = n0 / 192;
        int r = n0 - h * 192;
        __half* dst = (r < 64) ? g_Qh : ((r < 128) ? g_Kh : g_Vh);
        float scl = (r < 64) ? 0.125f : 1.f;
        #pragma unroll
        for (int mt = 0; mt < 4; mt++) {
            #pragma unroll
            for (int half_ = 0; half_ < 2; half_++) {
                int m  = bm * 256 + wrow * 64 + mt * 16 + g + half_ * 8;
                int b_ = m >> 11;
                int s_ = m & 2047;
                size_t o = ((((size_t)b_ * NH + h) * SEQ) + s_) * HD + (r & 63);
                *(__half2*)(dst + o) = __floats2half2_rn((acc[mt][nt][half_ * 2]     + bx) * scl,
                                                         (acc[mt][nt][half_ * 2 + 1] + by) * scl);
            }
        }
    }
}

// ---------------------------------------------------------------------------
// Kernel 2: causal flash attention (round-9 config, known roofline-optimal).
// 8 warps x 32 q-rows = 256 q-rows/CTA, 256 threads, cp.async dbl-buffer.
// ---------------------------------------------------------------------------
#define QSTR 72
#define KSTR 72
#define KV_B (64*KSTR*2)
#define CTAQ 256
#define L2E 1.44269504f

__global__ __launch_bounds__(256, 1) void attn_fa(float* __restrict__ out)
{
    extern __shared__ __half smh[];
    __half* Qs = smh;
    __half* Ks = Qs + CTAQ * QSTR;
    __half* Vs = Ks + 2 * 64 * KSTR;
    const uint32_t uQ = smem_u32(Qs);
    const uint32_t uK = smem_u32(Ks);
    const uint32_t uV = smem_u32(Vs);

    const int tid  = threadIdx.x;
    const int wid  = tid >> 5;
    const int lane = tid & 31;
    const int g = lane >> 2, t = lane & 3;
    const int qt = gridDim.x - 1 - blockIdx.x;
    const int h = blockIdx.y, b = blockIdx.z;
    const int wb = wid * 32;
    const int qbase = qt * CTAQ;
    const int row0 = qbase + wb + g;

    const size_t hb = (((size_t)b * NH + h) * SEQ) * HD;
    const int nkb = (qt + 1) * (CTAQ / 64);

    int kvrow[2], kvcol[2];
    #pragma unroll
    for (int i = 0; i < 2; i++) {
        int idx = tid + i * 256;
        kvrow[i] = idx >> 3;
        kvcol[i] = (idx & 7) * 8;
    }
    auto issueKV = [&](int kb, int slot) {
        const __half* ks = g_Kh + hb + (size_t)kb * 64 * HD;
        const __half* vs = g_Vh + hb + (size_t)kb * 64 * HD;
        #pragma unroll
        for (int i = 0; i < 2; i++) {
            cp16(uK + slot * KV_B + (kvrow[i] * KSTR + kvcol[i]) * 2, ks + kvrow[i] * HD + kvcol[i]);
            cp16(uV + slot * KV_B + (kvrow[i] * KSTR + kvcol[i]) * 2, vs + kvrow[i] * HD + kvcol[i]);
        }
    };

    issueKV(0, 0);
    CP_COMMIT();
    {
        const __half* qs = g_Qh + hb + (size_t)qbase * HD;
        #pragma unroll
        for (int i = 0; i < 8; i++) {
            int idx = tid + i * 256;
            int r = idx >> 3, c = (idx & 7) * 8;
            cp16(uQ + (r * QSTR + c) * 2, qs + r * HD + c);
        }
    }
    CP_COMMIT();
    CP_WAIT(0);
    __syncthreads();

    uint32_t aq[2][4][4];
    {
        const uint32_t qb = uQ + (wb + (lane & 15)) * (QSTR * 2) + ((lane & 16) ? 16 : 0);
        #pragma unroll
        for (int mt = 0; mt < 2; mt++)
            #pragma unroll
            for (int kt = 0; kt < 4; kt++)
                ldsm4(aq[mt][kt], qb + mt * 16 * (QSTR * 2) + kt * 32);
    }

    float o[2][8][4];
    #pragma unroll
    for (int mt = 0; mt < 2; mt++)
        #pragma unroll
        for (int nt = 0; nt < 8; nt++)
            #pragma unroll
            for (int e = 0; e < 4; e++) o[mt][nt][e] = 0.f;
    float m00 = -1e30f, m01 = -1e30f, m10 = -1e30f, m11 = -1e30f;
    float l00 = 0.f, l01 = 0.f, l10 = 0.f, l11 = 0.f;

    const uint32_t kfOff = ((lane & 7) + ((lane & 16) ? 8 : 0)) * (KSTR * 2) + ((lane & 8) ? 16 : 0);
    const uint32_t vfOff = ((lane & 7) + ((lane & 8) ? 8 : 0)) * (KSTR * 2) + ((lane & 16) ? 16 : 0);

    #pragma unroll 1
    for (int kb = 0; kb < nkb; kb++) {
        const int slot = kb & 1;
        if (kb + 1 < nkb) { issueKV(kb + 1, slot ^ 1); CP_COMMIT(); }
        if (kb + 1 < nkb) { CP_WAIT(1); } else { CP_WAIT(0); }
        __syncthreads();

        if (kb * 64 <= qbase + wb + 31) {
            float s[2][8][4];
            #pragma unroll
            for (int mt = 0; mt < 2; mt++)
                #pragma unroll
                for (int nt = 0; nt < 8; nt++)
                    #pragma unroll
                    for (int e = 0; e < 4; e++) s[mt][nt][e] = 0.f;

            const uint32_t kbase_ = uK + slot * KV_B + kfOff;
            #pragma unroll
            for (int kt = 0; kt < 4; kt++) {
                uint32_t kf[4][4];
                #pragma unroll
                for (int ntp = 0; ntp < 4; ntp++)
                    ldsm4(kf[ntp], kbase_ + ntp * 16 * (KSTR * 2) + kt * 32);
                #pragma unroll
                for (int nt = 0; nt < 8; nt++) {
                    uint32_t b0 = kf[nt >> 1][(nt & 1) * 2], b1 = kf[nt >> 1][(nt & 1) * 2 + 1];
                    mma16(s[0][nt], aq[0][kt], b0, b1);
                    mma16(s[1][nt], aq[1][kt], b0, b1);
                }
            }

            if (kb * 64 + 63 > qbase + wb) {
                #pragma unroll
                for (int nt = 0; nt < 8; nt++) {
                    int col = kb * 64 + nt * 8 + 2 * t;
                    if (col     > row0)      s[0][nt][0] = -1e30f;
                    if (col + 1 > row0)      s[0][nt][1] = -1e30f;
                    if (col     > row0 + 8)  s[0][nt][2] = -1e30f;
                    if (col + 1 > row0 + 8)  s[0][nt][3] = -1e30f;
                    if (col     > row0 + 16) s[1][nt][0] = -1e30f;
                    if (col + 1 > row0 + 16) s[1][nt][1] = -1e30f;
                    if (col     > row0 + 24) s[1][nt][2] = -1e30f;
                    if (col + 1 > row0 + 24) s[1][nt][3] = -1e30f;
                }
            }

            float b00 = -1e30f, b01 = -1e30f, b10 = -1e30f, b11 = -1e30f;
            #pragma unroll
            for (int nt = 0; nt < 8; nt++) {
                b00 = fmaxf(b00, fmaxf(s[0][nt][0], s[0][nt][1]));
                b01 = fmaxf(b01, fmaxf(s[0][nt][2], s[0][nt][3]));
                b10 = fmaxf(b10, fmaxf(s[1][nt][0], s[1][nt][1]));
                b11 = fmaxf(b11, fmaxf(s[1][nt][2], s[1][nt][3]));
            }
            #pragma unroll
            for (int d = 1; d <= 2; d <<= 1) {
                b00 = fmaxf(b00, __shfl_xor_sync(0xffffffffu, b00, d));
                b01 = fmaxf(b01, __shfl_xor_sync(0xffffffffu, b01, d));
                b10 = fmaxf(b10, __shfl_xor_sync(0xffffffffu, b10, d));
                b11 = fmaxf(b11, __shfl_xor_sync(0xffffffffu, b11, d));
            }
            float n00 = fmaxf(m00, b00), n01 = fmaxf(m01, b01);
            float n10 = fmaxf(m10, b10), n11 = fmaxf(m11, b11);
            float c00 = exp2f((m00 - n00) * L2E), c01 = exp2f((m01 - n01) * L2E);
            float c10 = exp2f((m10 - n10) * L2E), c11 = exp2f((m11 - n11) * L2E);

            uint32_t pc[2][8][2];
            float s00 = 0.f, s01 = 0.f, s10 = 0.f, s11 = 0.f;
            #pragma unroll
            for (int nt = 0; nt < 8; nt++) {
                float p0 = exp2f((s[0][nt][0] - n00) * L2E);
                float p1 = exp2f((s[0][nt][1] - n00) * L2E);
                float p2 = exp2f((s[0][nt][2] - n01) * L2E);
                float p3 = exp2f((s[0][nt][3] - n01) * L2E);
                float q0 = exp2f((s[1][nt][0] - n10) * L2E);
                float q1 = exp2f((s[1][nt][1] - n10) * L2E);
                float q2 = exp2f((s[1][nt][2] - n11) * L2E);
                float q3 = exp2f((s[1][nt][3] - n11) * L2E);
                s00 += p0 + p1; s01 += p2 + p3;
                s10 += q0 + q1; s11 += q2 + q3;
                pc[0][nt][0] = pack2(p0, p1);
                pc[0][nt][1] = pack2(p2, p3);
                pc[1][nt][0] = pack2(q0, q1);
                pc[1][nt][1] = pack2(q2, q3);
            }
            #pragma unroll
            for (int d = 1; d <= 2; d <<= 1) {
                s00 += __shfl_xor_sync(0xffffffffu, s00, d);
                s01 += __shfl_xor_sync(0xffffffffu, s01, d);
                s10 += __shfl_xor_sync(0xffffffffu, s10, d);
                s11 += __shfl_xor_sync(0xffffffffu, s11, d);
            }
            l00 = l00 * c00 + s00; l01 = l01 * c01 + s01;
            l10 = l10 * c10 + s10; l11 = l11 * c11 + s11;
            m00 = n00; m01 = n01; m10 = n10; m11 = n11;

            #pragma unroll
            for (int nt = 0; nt < 8; nt++) {
                o[0][nt][0] *= c00; o[0][nt][1] *= c00;
                o[0][nt][2] *= c01; o[0][nt][3] *= c01;
                o[1][nt][0] *= c10; o[1][nt][1] *= c10;
                o[1][nt][2] *= c11; o[1][nt][3] *= c11;
            }

            const uint32_t vbase_ = uV + slot * KV_B + vfOff;
            #pragma unroll
            for (int kt = 0; kt < 4; kt++) {
                uint32_t vf[4][4];
                #pragma unroll
                for (int ntp = 0; ntp < 4; ntp++)
                    ldsm4t(vf[ntp], vbase_ + kt * 16 * (KSTR * 2) + ntp * 32);
                uint32_t ap0[4] = {pc[0][2*kt][0], pc[0][2*kt][1], pc[0][2*kt+1][0], pc[0][2*kt+1][1]};
                uint32_t ap1[4] = {pc[1][2*kt][0], pc[1][2*kt][1], pc[1][2*kt+1][0], pc[1][2*kt+1][1]};
                #pragma unroll
                for (int nt = 0; nt < 8; nt++) {
                    uint32_t b0 = vf[nt >> 1][(nt & 1) * 2], b1 = vf[nt >> 1][(nt & 1) * 2 + 1];
                    mma16(o[0][nt], ap0, b0, b1);
                    mma16(o[1][nt], ap1, b0, b1);
                }
            }
        }

        __syncthreads();
    }

    const float i00 = 1.f / l00, i01 = 1.f / l01;
    const float i10 = 1.f / l10, i11 = 1.f / l11;
    float* w00 = out + ((size_t)b * SEQ + row0) * DM + h * HD + 2 * t;
    float* w01 = out + ((size_t)b * SEQ + row0 + 8) * DM + h * HD + 2 * t;
    float* w10 = out + ((size_t)b * SEQ + row0 + 16) * DM + h * HD + 2 * t;
    float* w11 = out + ((size_t)b * SEQ + row0 + 24) * DM + h * HD + 2 * t;
    #pragma unroll
    for (int nt = 0; nt < 8; nt++) {
        *(float2*)(w00 + nt * 8) = make_float2(o[0][nt][0] * i00, o[0][nt][1] * i00);
        *(float2*)(w01 + nt * 8) = make_float2(o[0][nt][2] * i01, o[0][nt][3] * i01);
        *(float2*)(w10 + nt * 8) = make_float2(o[1][nt][0] * i10, o[1][nt][1] * i10);
        *(float2*)(w11 + nt * 8) = make_float2(o[1][nt][2] * i11, o[1][nt][3] * i11);
    }
}

// ---------------------------------------------------------------------------
extern "C" void kernel_launch(void* const* d_in, const int* in_sizes, int n_in,
                              void* d_out, int out_size)
{
    (void)in_sizes; (void)n_in; (void)out_size;
    const float* x    = (const float*)d_in[0];
    const float* Wqkv = (const float*)d_in[1];
    const float* bqkv = (const float*)d_in[2];
    float* out = (float*)d_out;

    cvt_all<<<NWB + NXB, 256>>>(x, Wqkv);

    const int gemm_smem = NSTG * (SA_B + SB_B);              // 165888 B
    cudaFuncSetAttribute(qkv_gemm, cudaFuncAttributeMaxDynamicSharedMemorySize, gemm_smem);
    dim3 ggrid(N_TOT / 128, M_TOT / 256);                    // (24, 32)
    qkv_gemm<<<ggrid, 256, gemm_smem>>>(bqkv);

    const int attn_smem = (CTAQ * QSTR + 4 * 64 * KSTR) * 2; // 73728 B
    cudaFuncSetAttribute(attn_fa, cudaFuncAttributeMaxDynamicSharedMemorySize, attn_smem);
    dim3 agrid(SEQ / CTAQ, NH, BZ);                          // (8, 16, 4)
    attn_fa<<<agrid, 256, attn_smem>>>(out);
}

// round 12
// speedup vs baseline: 1.1461x; 1.0507x over previous
#include <cuda_runtime.h>
#include <cuda_fp16.h>
#include <cstdint>

// Problem constants
#define BZ 4
#define SEQ 2048
#define DM 1024
#define NH 16
#define HD 64
#define M_TOT 8192
#define N_TOT 3072

// Scratch (fp16)
__device__ __half g_Qh[BZ*NH*SEQ*HD];
__device__ __half g_Kh[BZ*NH*SEQ*HD];
__device__ __half g_Vh[BZ*NH*SEQ*HD];
__device__ __half g_Xh[M_TOT*DM];
__device__ __half g_Wh[(size_t)DM*N_TOT];   // W fp16, NATIVE [k][n] layout

// ---------------------------------------------------------------------------
// helpers
// ---------------------------------------------------------------------------
__device__ __forceinline__ void mma16(float* c, const uint32_t* a, uint32_t b0, uint32_t b1){
    asm volatile("mma.sync.aligned.m16n8k16.row.col.f32.f16.f16.f32 "
        "{%0,%1,%2,%3}, {%4,%5,%6,%7}, {%8,%9}, {%0,%1,%2,%3};"
        : "+f"(c[0]), "+f"(c[1]), "+f"(c[2]), "+f"(c[3])
        : "r"(a[0]), "r"(a[1]), "r"(a[2]), "r"(a[3]), "r"(b0), "r"(b1));
}
__device__ __forceinline__ void ldsm4(uint32_t* r, uint32_t addr){
    asm volatile("ldmatrix.sync.aligned.m8n8.x4.shared.b16 {%0,%1,%2,%3}, [%4];"
        : "=r"(r[0]), "=r"(r[1]), "=r"(r[2]), "=r"(r[3]) : "r"(addr));
}
__device__ __forceinline__ void ldsm4t(uint32_t* r, uint32_t addr){
    asm volatile("ldmatrix.sync.aligned.m8n8.x4.trans.shared.b16 {%0,%1,%2,%3}, [%4];"
        : "=r"(r[0]), "=r"(r[1]), "=r"(r[2]), "=r"(r[3]) : "r"(addr));
}
__device__ __forceinline__ uint32_t pack2(float lo, float hi){
    uint32_t r; asm("cvt.rn.f16x2.f32 %0, %1, %2;" : "=r"(r) : "f"(hi), "f"(lo)); return r;
}
__device__ __forceinline__ uint32_t smem_u32(const void* p){
    uint32_t a;
    asm("{ .reg .u64 t; cvta.to.shared.u64 t, %1; cvt.u32.u64 %0, t; }" : "=r"(a) : "l"(p));
    return a;
}
__device__ __forceinline__ void cp16(uint32_t dst, const void* src){
    asm volatile("cp.async.cg.shared.global [%0], [%1], 16;" :: "r"(dst), "l"(src));
}
#define CP_COMMIT() asm volatile("cp.async.commit_group;" ::: "memory")
#define CP_WAIT(n)  asm volatile("cp.async.wait_group %0;" :: "n"(n) : "memory")

// ---------------------------------------------------------------------------
// Prepass: pure elementwise fp32 -> fp16 for x and W (both coalesced).
// ---------------------------------------------------------------------------
__global__ __launch_bounds__(256) void cvt_all(const float* __restrict__ x,
                                               const float* __restrict__ W)
{
    const size_t NX = (size_t)M_TOT * DM / 4;
    const size_t NW = (size_t)DM * N_TOT / 4;
    const size_t gid = (size_t)blockIdx.x * blockDim.x + threadIdx.x;
    const size_t stride = (size_t)gridDim.x * blockDim.x;
    for (size_t i = gid; i < NX; i += stride) {
        float4 v = ((const float4*)x)[i];
        __half2* o = (__half2*)(g_Xh + i * 4);
        o[0] = __floats2half2_rn(v.x, v.y);
        o[1] = __floats2half2_rn(v.z, v.w);
    }
    for (size_t i = gid; i < NW; i += stride) {
        float4 v = ((const float4*)W)[i];
        __half2* o = (__half2*)(g_Wh + i * 4);
        o[0] = __floats2half2_rn(v.x, v.y);
        o[1] = __floats2half2_rn(v.z, v.w);
    }
}

// ---------------------------------------------------------------------------
// Kernel 1: QKV GEMM, fp16 mma, BK=64, 3-stage cp.async.
// A [m][k] via ldsm4 (non-trans); B native [k][n] via ldsm4t (trans),
// mirroring the proven attention-V fragment path.
// CTA tile 256x128, 8 warps (4M x 2N), warp tile 64x64, 256 threads.
// ---------------------------------------------------------------------------
#define ASTR 72                  // halves per A row (64 + 8 pad)
#define BSTR 136                 // halves per B row (128 + 8 pad)
#define SA_H (256*ASTR)
#define SB_H (64*BSTR)
#define SA_B (SA_H*2)            // 36864 B
#define SB_B (SB_H*2)            // 17408 B
#define NKB  (DM/64)             // 16
#define NSTG 3

__global__ __launch_bounds__(256, 1) void qkv_gemm(const float* __restrict__ bias)
{
    extern __shared__ __half smh[];
    __half* sA = smh;
    __half* sB = smh + NSTG * SA_H;
    const uint32_t uA = smem_u32(sA);
    const uint32_t uB = smem_u32(sB);

    const int tid  = threadIdx.x;
    const int wid  = tid >> 5;
    const int lane = tid & 31;
    const int g = lane >> 2, t = lane & 3;
    const int wrow = wid & 3;      // m = wrow*64
    const int wcol = wid >> 2;     // n = wcol*64
    const int bm = blockIdx.y, bn = blockIdx.x;

    const __half* Ab = g_Xh + (size_t)(bm * 256) * DM;
    const __half* Bb = g_Wh + (size_t)bn * 128;   // [k][n], col offset bn*128

    // A: 2048 16B-chunks (8/thread), rows of 64 k = 8 chunks
    int arow[8], acol[8];
    #pragma unroll
    for (int l = 0; l < 8; l++) {
        int idx = tid + l * 256;
        arow[l] = idx >> 3;
        acol[l] = (idx & 7) * 8;
    }
    // B: 64 k-rows x 128 n = 1024 chunks (4/thread), 16 chunks/row
    int brow[4], bcol[4];
    #pragma unroll
    for (int l = 0; l < 4; l++) {
        int idx = tid + l * 256;
        brow[l] = idx >> 4;
        bcol[l] = (idx & 15) * 8;
    }

    auto issue = [&](int slot, int k0) {
        uint32_t pa = uA + slot * SA_B;
        uint32_t pb = uB + slot * SB_B;
        #pragma unroll
        for (int l = 0; l < 8; l++)
            cp16(pa + (arow[l] * ASTR + acol[l]) * 2, Ab + (size_t)arow[l] * DM + k0 + acol[l]);
        #pragma unroll
        for (int l = 0; l < 4; l++)
            cp16(pb + (brow[l] * BSTR + bcol[l]) * 2, Bb + (size_t)(k0 + brow[l]) * N_TOT + bcol[l]);
    };

    float acc[4][8][4];
    #pragma unroll
    for (int mt = 0; mt < 4; mt++)
        #pragma unroll
        for (int nt = 0; nt < 8; nt++)
            #pragma unroll
            for (int e = 0; e < 4; e++) acc[mt][nt][e] = 0.f;

    issue(0, 0);   CP_COMMIT();
    issue(1, 64);  CP_COMMIT();
    CP_WAIT(1);                    // slot 0 ready
    __syncthreads();

    const uint32_t aBase = uA + (wrow * 64 + (lane & 15)) * (ASTR * 2) + ((lane & 16) ? 16 : 0);
    // trans-B base: rows = k (8 + 8 via lane&8), col halves: lane&16 -> +8 n
    const uint32_t bBase = uB + ((lane & 7) + ((lane & 8) ? 8 : 0)) * (BSTR * 2)
                         + ((lane & 16) ? 16 : 0) + wcol * 64 * 2;

    int slot = 0;
    #pragma unroll 1
    for (int kb = 0; kb < NKB; kb++) {
        const uint32_t aS = aBase + slot * SA_B;
        const uint32_t bS = bBase + slot * SB_B;

        // ---- sub-batch 0: kt 0,1 ----
        uint32_t af[2][4][4], bf[2][4][4];
        #pragma unroll
        for (int kt = 0; kt < 2; kt++) {
            #pragma unroll
            for (int mt = 0; mt < 4; mt++)
                ldsm4(af[kt][mt], aS + mt * 16 * (ASTR * 2) + kt * 32);
            #pragma unroll
            for (int ntp = 0; ntp < 4; ntp++)
                ldsm4t(bf[kt][ntp], bS + kt * 16 * (BSTR * 2) + ntp * 32);
        }

        if (kb + 2 < NKB) {
            int ns = slot + 2; if (ns >= NSTG) ns -= NSTG;
            issue(ns, (kb + 2) * 64);
            CP_COMMIT();
        }

        #pragma unroll
        for (int kt = 0; kt < 2; kt++)
            #pragma unroll
            for (int mt = 0; mt < 4; mt++)
                #pragma unroll
                for (int nt = 0; nt < 8; nt++)
                    mma16(acc[mt][nt], af[kt][mt],
                          bf[kt][nt >> 1][(nt & 1) * 2], bf[kt][nt >> 1][(nt & 1) * 2 + 1]);

        // ---- sub-batch 1: kt 2,3 ----
        #pragma unroll
        for (int kt = 0; kt < 2; kt++) {
            #pragma unroll
            for (int mt = 0; mt < 4; mt++)
                ldsm4(af[kt][mt], aS + mt * 16 * (ASTR * 2) + (kt + 2) * 32);
            #pragma unroll
            for (int ntp = 0; ntp < 4; ntp++)
                ldsm4t(bf[kt][ntp], bS + (kt + 2) * 16 * (BSTR * 2) + ntp * 32);
        }
        #pragma unroll
        for (int kt = 0; kt < 2; kt++)
            #pragma unroll
            for (int mt = 0; mt < 4; mt++)
                #pragma unroll
                for (int nt = 0; nt < 8; nt++)
                    mma16(acc[mt][nt], af[kt][mt],
                          bf[kt][nt >> 1][(nt & 1) * 2], bf[kt][nt >> 1][(nt & 1) * 2 + 1]);

        if (kb + 2 < NKB)      { CP_WAIT(1); }
        else if (kb + 1 < NKB) { CP_WAIT(0); }
        __syncthreads();
        if (++slot == NSTG) slot = 0;
    }

    // Epilogue
    #pragma unroll
    for (int nt = 0; nt < 8; nt++) {
        int n0 = bn * 128 + wcol * 64 + nt * 8 + 2 * t;
        float bx = __ldg(&bias[n0]), by = __ldg(&bias[n0 + 1]);
        int h = n0 / 192;
        int r = n0 - h * 192;
        __half* dst = (r < 64) ? g_Qh : ((r < 128) ? g_Kh : g_Vh);
        float scl = (r < 64) ? 0.125f : 1.f;
        #pragma unroll
        for (int mt = 0; mt < 4; mt++) {
            #pragma unroll
            for (int half_ = 0; half_ < 2; half_++) {
                int m  = bm * 256 + wrow * 64 + mt * 16 + g + half_ * 8;
                int b_ = m >> 11;
                int s_ = m & 2047;
                size_t o = ((((size_t)b_ * NH + h) * SEQ) + s_) * HD + (r & 63);
                *(__half2*)(dst + o) = __floats2half2_rn((acc[mt][nt][half_ * 2]     + bx) * scl,
                                                         (acc[mt][nt][half_ * 2 + 1] + by) * scl);
            }
        }
    }
}

// ---------------------------------------------------------------------------
// Kernel 2: causal flash attention (round-9 config, roofline-optimal).
// 8 warps x 32 q-rows = 256 q-rows/CTA, 256 threads, cp.async dbl-buffer.
// ---------------------------------------------------------------------------
#define QSTR 72
#define KSTR 72
#define KV_B (64*KSTR*2)
#define CTAQ 256
#define L2E 1.44269504f

__global__ __launch_bounds__(256, 1) void attn_fa(float* __restrict__ out)
{
    extern __shared__ __half smh[];
    __half* Qs = smh;
    __half* Ks = Qs + CTAQ * QSTR;
    __half* Vs = Ks + 2 * 64 * KSTR;
    const uint32_t uQ = smem_u32(Qs);
    const uint32_t uK = smem_u32(Ks);
    const uint32_t uV = smem_u32(Vs);

    const int tid  = threadIdx.x;
    const int wid  = tid >> 5;
    const int lane = tid & 31;
    const int g = lane >> 2, t = lane & 3;
    const int qt = gridDim.x - 1 - blockIdx.x;
    const int h = blockIdx.y, b = blockIdx.z;
    const int wb = wid * 32;
    const int qbase = qt * CTAQ;
    const int row0 = qbase + wb + g;

    const size_t hb = (((size_t)b * NH + h) * SEQ) * HD;
    const int nkb = (qt + 1) * (CTAQ / 64);

    int kvrow[2], kvcol[2];
    #pragma unroll
    for (int i = 0; i < 2; i++) {
        int idx = tid + i * 256;
        kvrow[i] = idx >> 3;
        kvcol[i] = (idx & 7) * 8;
    }
    auto issueKV = [&](int kb, int slot) {
        const __half* ks = g_Kh + hb + (size_t)kb * 64 * HD;
        const __half* vs = g_Vh + hb + (size_t)kb * 64 * HD;
        #pragma unroll
        for (int i = 0; i < 2; i++) {
            cp16(uK + slot * KV_B + (kvrow[i] * KSTR + kvcol[i]) * 2, ks + kvrow[i] * HD + kvcol[i]);
            cp16(uV + slot * KV_B + (kvrow[i] * KSTR + kvcol[i]) * 2, vs + kvrow[i] * HD + kvcol[i]);
        }
    };

    issueKV(0, 0);
    CP_COMMIT();
    {
        const __half* qs = g_Qh + hb + (size_t)qbase * HD;
        #pragma unroll
        for (int i = 0; i < 8; i++) {
            int idx = tid + i * 256;
            int r = idx >> 3, c = (idx & 7) * 8;
            cp16(uQ + (r * QSTR + c) * 2, qs + r * HD + c);
        }
    }
    CP_COMMIT();
    CP_WAIT(0);
    __syncthreads();

    uint32_t aq[2][4][4];
    {
        const uint32_t qb = uQ + (wb + (lane & 15)) * (QSTR * 2) + ((lane & 16) ? 16 : 0);
        #pragma unroll
        for (int mt = 0; mt < 2; mt++)
            #pragma unroll
            for (int kt = 0; kt < 4; kt++)
                ldsm4(aq[mt][kt], qb + mt * 16 * (QSTR * 2) + kt * 32);
    }

    float o[2][8][4];
    #pragma unroll
    for (int mt = 0; mt < 2; mt++)
        #pragma unroll
        for (int nt = 0; nt < 8; nt++)
            #pragma unroll
            for (int e = 0; e < 4; e++) o[mt][nt][e] = 0.f;
    float m00 = -1e30f, m01 = -1e30f, m10 = -1e30f, m11 = -1e30f;
    float l00 = 0.f, l01 = 0.f, l10 = 0.f, l11 = 0.f;

    const uint32_t kfOff = ((lane & 7) + ((lane & 16) ? 8 : 0)) * (KSTR * 2) + ((lane & 8) ? 16 : 0);
    const uint32_t vfOff = ((lane & 7) + ((lane & 8) ? 8 : 0)) * (KSTR * 2) + ((lane & 16) ? 16 : 0);

    #pragma unroll 1
    for (int kb = 0; kb < nkb; kb++) {
        const int slot = kb & 1;
        if (kb + 1 < nkb) { issueKV(kb + 1, slot ^ 1); CP_COMMIT(); }
        if (kb + 1 < nkb) { CP_WAIT(1); } else { CP_WAIT(0); }
        __syncthreads();

        if (kb * 64 <= qbase + wb + 31) {
            float s[2][8][4];
            #pragma unroll
            for (int mt = 0; mt < 2; mt++)
                #pragma unroll
                for (int nt = 0; nt < 8; nt++)
                    #pragma unroll
                    for (int e = 0; e < 4; e++) s[mt][nt][e] = 0.f;

            const uint32_t kbase_ = uK + slot * KV_B + kfOff;
            #pragma unroll
            for (int kt = 0; kt < 4; kt++) {
                uint32_t kf[4][4];
                #pragma unroll
                for (int ntp = 0; ntp < 4; ntp++)
                    ldsm4(kf[ntp], kbase_ + ntp * 16 * (KSTR * 2) + kt * 32);
                #pragma unroll
                for (int nt = 0; nt < 8; nt++) {
                    uint32_t b0 = kf[nt >> 1][(nt & 1) * 2], b1 = kf[nt >> 1][(nt & 1) * 2 + 1];
                    mma16(s[0][nt], aq[0][kt], b0, b1);
                    mma16(s[1][nt], aq[1][kt], b0, b1);
                }
            }

            if (kb * 64 + 63 > qbase + wb) {
                #pragma unroll
                for (int nt = 0; nt < 8; nt++) {
                    int col = kb * 64 + nt * 8 + 2 * t;
                    if (col     > row0)      s[0][nt][0] = -1e30f;
                    if (col + 1 > row0)      s[0][nt][1] = -1e30f;
                    if (col     > row0 + 8)  s[0][nt][2] = -1e30f;
                    if (col + 1 > row0 + 8)  s[0][nt][3] = -1e30f;
                    if (col     > row0 + 16) s[1][nt][0] = -1e30f;
                    if (col + 1 > row0 + 16) s[1][nt][1] = -1e30f;
                    if (col     > row0 + 24) s[1][nt][2] = -1e30f;
                    if (col + 1 > row0 + 24) s[1][nt][3] = -1e30f;
                }
            }

            float b00 = -1e30f, b01 = -1e30f, b10 = -1e30f, b11 = -1e30f;
            #pragma unroll
            for (int nt = 0; nt < 8; nt++) {
                b00 = fmaxf(b00, fmaxf(s[0][nt][0], s[0][nt][1]));
                b01 = fmaxf(b01, fmaxf(s[0][nt][2], s[0][nt][3]));
                b10 = fmaxf(b10, fmaxf(s[1][nt][0], s[1][nt][1]));
                b11 = fmaxf(b11, fmaxf(s[1][nt][2], s[1][nt][3]));
            }
            #pragma unroll
            for (int d = 1; d <= 2; d <<= 1) {
                b00 = fmaxf(b00, __shfl_xor_sync(0xffffffffu, b00, d));
                b01 = fmaxf(b01, __shfl_xor_sync(0xffffffffu, b01, d));
                b10 = fmaxf(b10, __shfl_xor_sync(0xffffffffu, b10, d));
                b11 = fmaxf(b11, __shfl_xor_sync(0xffffffffu, b11, d));
            }
            float n00 = fmaxf(m00, b00), n01 = fmaxf(m01, b01);
            float n10 = fmaxf(m10, b10), n11 = fmaxf(m11, b11);
            float c00 = exp2f((m00 - n00) * L2E), c01 = exp2f((m01 - n01) * L2E);
            float c10 = exp2f((m10 - n10) * L2E), c11 = exp2f((m11 - n11) * L2E);

            uint32_t pc[2][8][2];
            float s00 = 0.f, s01 = 0.f, s10 = 0.f, s11 = 0.f;
            #pragma unroll
            for (int nt = 0; nt < 8; nt++) {
                float p0 = exp2f((s[0][nt][0] - n00) * L2E);
                float p1 = exp2f((s[0][nt][1] - n00) * L2E);
                float p2 = exp2f((s[0][nt][2] - n01) * L2E);
                float p3 = exp2f((s[0][nt][3] - n01) * L2E);
                float q0 = exp2f((s[1][nt][0] - n10) * L2E);
                float q1 = exp2f((s[1][nt][1] - n10) * L2E);
                float q2 = exp2f((s[1][nt][2] - n11) * L2E);
                float q3 = exp2f((s[1][nt][3] - n11) * L2E);
                s00 += p0 + p1; s01 += p2 + p3;
                s10 += q0 + q1; s11 += q2 + q3;
                pc[0][nt][0] = pack2(p0, p1);
                pc[0][nt][1] = pack2(p2, p3);
                pc[1][nt][0] = pack2(q0, q1);
                pc[1][nt][1] = pack2(q2, q3);
            }
            #pragma unroll
            for (int d = 1; d <= 2; d <<= 1) {
                s00 += __shfl_xor_sync(0xffffffffu, s00, d);
                s01 += __shfl_xor_sync(0xffffffffu, s01, d);
                s10 += __shfl_xor_sync(0xffffffffu, s10, d);
                s11 += __shfl_xor_sync(0xffffffffu, s11, d);
            }
            l00 = l00 * c00 + s00; l01 = l01 * c01 + s01;
            l10 = l10 * c10 + s10; l11 = l11 * c11 + s11;
            m00 = n00; m01 = n01; m10 = n10; m11 = n11;

            #pragma unroll
            for (int nt = 0; nt < 8; nt++) {
                o[0][nt][0] *= c00; o[0][nt][1] *= c00;
                o[0][nt][2] *= c01; o[0][nt][3] *= c01;
                o[1][nt][0] *= c10; o[1][nt][1] *= c10;
                o[1][nt][2] *= c11; o[1][nt][3] *= c11;
            }

            const uint32_t vbase_ = uV + slot * KV_B + vfOff;
            #pragma unroll
            for (int kt = 0; kt < 4; kt++) {
                uint32_t vf[4][4];
                #pragma unroll
                for (int ntp = 0; ntp < 4; ntp++)
                    ldsm4t(vf[ntp], vbase_ + kt * 16 * (KSTR * 2) + ntp * 32);
                uint32_t ap0[4] = {pc[0][2*kt][0], pc[0][2*kt][1], pc[0][2*kt+1][0], pc[0][2*kt+1][1]};
                uint32_t ap1[4] = {pc[1][2*kt][0], pc[1][2*kt][1], pc[1][2*kt+1][0], pc[1][2*kt+1][1]};
                #pragma unroll
                for (int nt = 0; nt < 8; nt++) {
                    uint32_t b0 = vf[nt >> 1][(nt & 1) * 2], b1 = vf[nt >> 1][(nt & 1) * 2 + 1];
                    mma16(o[0][nt], ap0, b0, b1);
                    mma16(o[1][nt], ap1, b0, b1);
                }
            }
        }

        __syncthreads();
    }

    const float i00 = 1.f / l00, i01 = 1.f / l01;
    const float i10 = 1.f / l10, i11 = 1.f / l11;
    float* w00 = out + ((size_t)b * SEQ + row0) * DM + h * HD + 2 * t;
    float* w01 = out + ((size_t)b * SEQ + row0 + 8) * DM + h * HD + 2 * t;
    float* w10 = out + ((size_t)b * SEQ + row0 + 16) * DM + h * HD + 2 * t;
    float* w11 = out + ((size_t)b * SEQ + row0 + 24) * DM + h * HD + 2 * t;
    #pragma unroll
    for (int nt = 0; nt < 8; nt++) {
        *(float2*)(w00 + nt * 8) = make_float2(o[0][nt][0] * i00, o[0][nt][1] * i00);
        *(float2*)(w01 + nt * 8) = make_float2(o[0][nt][2] * i01, o[0][nt][3] * i01);
        *(float2*)(w10 + nt * 8) = make_float2(o[1][nt][0] * i10, o[1][nt][1] * i10);
        *(float2*)(w11 + nt * 8) = make_float2(o[1][nt][2] * i11, o[1][nt][3] * i11);
    }
}

// ---------------------------------------------------------------------------
extern "C" void kernel_launch(void* const* d_in, const int* in_sizes, int n_in,
                              void* d_out, int out_size)
{
    (void)in_sizes; (void)n_in; (void)out_size;
    const float* x    = (const float*)d_in[0];
    const float* Wqkv = (const float*)d_in[1];
    const float* bqkv = (const float*)d_in[2];
    float* out = (float*)d_out;

    cvt_all<<<888, 256>>>(x, Wqkv);   // 6 waves of 148

    const int gemm_smem = NSTG * (SA_B + SB_B);              // 162816 B
    cudaFuncSetAttribute(qkv_gemm, cudaFuncAttributeMaxDynamicSharedMemorySize, gemm_smem);
    dim3 ggrid(N_TOT / 128, M_TOT / 256);                    // (24, 32)
    qkv_gemm<<<ggrid, 256, gemm_smem>>>(bqkv);

    const int attn_smem = (CTAQ * QSTR + 4 * 64 * KSTR) * 2; // 73728 B
    cudaFuncSetAttribute(attn_fa, cudaFuncAttributeMaxDynamicSharedMemorySize, attn_smem);
    dim3 agrid(SEQ / CTAQ, NH, BZ);                          // (8, 16, 4)
    attn_fa<<<agrid, 256, attn_smem>>>(out);
}

// round 13
// speedup vs baseline: 1.2447x; 1.0860x over previous
#include <cuda_runtime.h>
#include <cuda_fp16.h>
#include <cstdint>

// Problem constants
#define BZ 4
#define SEQ 2048
#define DM 1024
#define NH 16
#define HD 64
#define M_TOT 8192
#define N_TOT 3072

// Scratch (fp16)
__device__ __half g_Qh[BZ*NH*SEQ*HD];
__device__ __half g_Kh[BZ*NH*SEQ*HD];
__device__ __half g_Vh[BZ*NH*SEQ*HD];
__device__ __half g_Xh[M_TOT*DM];
__device__ __half g_Wh[(size_t)DM*N_TOT];   // W fp16, NATIVE [k][n] layout

// ---------------------------------------------------------------------------
// helpers
// ---------------------------------------------------------------------------
__device__ __forceinline__ void mma16(float* c, const uint32_t* a, uint32_t b0, uint32_t b1){
    asm volatile("mma.sync.aligned.m16n8k16.row.col.f32.f16.f16.f32 "
        "{%0,%1,%2,%3}, {%4,%5,%6,%7}, {%8,%9}, {%0,%1,%2,%3};"
        : "+f"(c[0]), "+f"(c[1]), "+f"(c[2]), "+f"(c[3])
        : "r"(a[0]), "r"(a[1]), "r"(a[2]), "r"(a[3]), "r"(b0), "r"(b1));
}
__device__ __forceinline__ void ldsm4(uint32_t* r, uint32_t addr){
    asm volatile("ldmatrix.sync.aligned.m8n8.x4.shared.b16 {%0,%1,%2,%3}, [%4];"
        : "=r"(r[0]), "=r"(r[1]), "=r"(r[2]), "=r"(r[3]) : "r"(addr));
}
__device__ __forceinline__ void ldsm4t(uint32_t* r, uint32_t addr){
    asm volatile("ldmatrix.sync.aligned.m8n8.x4.trans.shared.b16 {%0,%1,%2,%3}, [%4];"
        : "=r"(r[0]), "=r"(r[1]), "=r"(r[2]), "=r"(r[3]) : "r"(addr));
}
__device__ __forceinline__ uint32_t pack2(float lo, float hi){
    uint32_t r; asm("cvt.rn.f16x2.f32 %0, %1, %2;" : "=r"(r) : "f"(hi), "f"(lo)); return r;
}
__device__ __forceinline__ uint32_t smem_u32(const void* p){
    uint32_t a;
    asm("{ .reg .u64 t; cvta.to.shared.u64 t, %1; cvt.u32.u64 %0, t; }" : "=r"(a) : "l"(p));
    return a;
}
__device__ __forceinline__ void cp16(uint32_t dst, const void* src){
    asm volatile("cp.async.cg.shared.global [%0], [%1], 16;" :: "r"(dst), "l"(src));
}
#define CP_COMMIT() asm volatile("cp.async.commit_group;" ::: "memory")
#define CP_WAIT(n)  asm volatile("cp.async.wait_group %0;" :: "n"(n) : "memory")

// ---------------------------------------------------------------------------
// Prepass: pure elementwise fp32 -> fp16 for x and W (coalesced).
// ---------------------------------------------------------------------------
__global__ __launch_bounds__(256) void cvt_all(const float* __restrict__ x,
                                               const float* __restrict__ W)
{
    const size_t NX = (size_t)M_TOT * DM / 4;
    const size_t NW = (size_t)DM * N_TOT / 4;
    const size_t gid = (size_t)blockIdx.x * blockDim.x + threadIdx.x;
    const size_t stride = (size_t)gridDim.x * blockDim.x;
    for (size_t i = gid; i < NX; i += stride) {
        float4 v = ((const float4*)x)[i];
        __half2* o = (__half2*)(g_Xh + i * 4);
        o[0] = __floats2half2_rn(v.x, v.y);
        o[1] = __floats2half2_rn(v.z, v.w);
    }
    for (size_t i = gid; i < NW; i += stride) {
        float4 v = ((const float4*)W)[i];
        __half2* o = (__half2*)(g_Wh + i * 4);
        o[0] = __floats2half2_rn(v.x, v.y);
        o[1] = __floats2half2_rn(v.z, v.w);
    }
}

// ---------------------------------------------------------------------------
// Kernel 1: QKV GEMM, fp16 mma, BK=64, 3-stage cp.async.
// CTA tile 256x96 (1024 CTAs -> 1.2% wave-quantization waste vs 15.6%).
// 8 warps (4M x 2N), warp tile 64x48. B native [k][n] via ldsm4t.
// ---------------------------------------------------------------------------
#define ASTR 72                  // halves per A row (64 + 8 pad)
#define BSTR 104                 // halves per B row (96 + 8 pad)
#define TN_G 96
#define SA_H (256*ASTR)
#define SB_H (64*BSTR)
#define SA_B (SA_H*2)            // 36864 B
#define SB_B (SB_H*2)            // 13312 B
#define NKB  (DM/64)             // 16
#define NSTG 3

__global__ __launch_bounds__(256, 1) void qkv_gemm(const float* __restrict__ bias)
{
    extern __shared__ __half smh[];
    __half* sA = smh;
    __half* sB = smh + NSTG * SA_H;
    const uint32_t uA = smem_u32(sA);
    const uint32_t uB = smem_u32(sB);

    const int tid  = threadIdx.x;
    const int wid  = tid >> 5;
    const int lane = tid & 31;
    const int g = lane >> 2, t = lane & 3;
    const int wrow = wid & 3;      // m = wrow*64
    const int wcol = wid >> 2;     // n = wcol*48
    const int bm = blockIdx.y, bn = blockIdx.x;

    const __half* Ab = g_Xh + (size_t)(bm * 256) * DM;
    const __half* Bb = g_Wh + (size_t)bn * TN_G;  // [k][n], col offset bn*96

    // A: 2048 16B-chunks (8/thread), 8 chunks per 64-k row
    int arow[8], acol[8];
    #pragma unroll
    for (int l = 0; l < 8; l++) {
        int idx = tid + l * 256;
        arow[l] = idx >> 3;
        acol[l] = (idx & 7) * 8;
    }
    // B: 64 k-rows x 96 n = 768 chunks (3/thread), 12 chunks/row
    int brow[3], bcol[3];
    #pragma unroll
    for (int l = 0; l < 3; l++) {
        int idx = tid + l * 256;
        brow[l] = idx / 12;
        bcol[l] = (idx % 12) * 8;
    }

    auto issue = [&](int slot, int k0) {
        uint32_t pa = uA + slot * SA_B;
        uint32_t pb = uB + slot * SB_B;
        #pragma unroll
        for (int l = 0; l < 8; l++)
            cp16(pa + (arow[l] * ASTR + acol[l]) * 2, Ab + (size_t)arow[l] * DM + k0 + acol[l]);
        #pragma unroll
        for (int l = 0; l < 3; l++)
            cp16(pb + (brow[l] * BSTR + bcol[l]) * 2, Bb + (size_t)(k0 + brow[l]) * N_TOT + bcol[l]);
    };

    float acc[4][6][4];
    #pragma unroll
    for (int mt = 0; mt < 4; mt++)
        #pragma unroll
        for (int nt = 0; nt < 6; nt++)
            #pragma unroll
            for (int e = 0; e < 4; e++) acc[mt][nt][e] = 0.f;

    issue(0, 0);   CP_COMMIT();
    issue(1, 64);  CP_COMMIT();
    CP_WAIT(1);
    __syncthreads();

    const uint32_t aBase = uA + (wrow * 64 + (lane & 15)) * (ASTR * 2) + ((lane & 16) ? 16 : 0);
    // trans-B base: rows = k (lane&7 + lane&8*), +8 n cols via lane&16
    const uint32_t bBase = uB + ((lane & 7) + ((lane & 8) ? 8 : 0)) * (BSTR * 2)
                         + ((lane & 16) ? 16 : 0) + wcol * 48 * 2;

    int slot = 0;
    #pragma unroll 1
    for (int kb = 0; kb < NKB; kb++) {
        const uint32_t aS = aBase + slot * SA_B;
        const uint32_t bS = bBase + slot * SB_B;

        // ---- sub-batch 0: kt 0,1 ----
        uint32_t af[2][4][4], bf[2][3][4];
        #pragma unroll
        for (int kt = 0; kt < 2; kt++) {
            #pragma unroll
            for (int mt = 0; mt < 4; mt++)
                ldsm4(af[kt][mt], aS + mt * 16 * (ASTR * 2) + kt * 32);
            #pragma unroll
            for (int ntp = 0; ntp < 3; ntp++)
                ldsm4t(bf[kt][ntp], bS + kt * 16 * (BSTR * 2) + ntp * 32);
        }

        if (kb + 2 < NKB) {
            int ns = slot + 2; if (ns >= NSTG) ns -= NSTG;
            issue(ns, (kb + 2) * 64);
            CP_COMMIT();
        }

        #pragma unroll
        for (int kt = 0; kt < 2; kt++)
            #pragma unroll
            for (int mt = 0; mt < 4; mt++)
                #pragma unroll
                for (int nt = 0; nt < 6; nt++)
                    mma16(acc[mt][nt], af[kt][mt],
                          bf[kt][nt >> 1][(nt & 1) * 2], bf[kt][nt >> 1][(nt & 1) * 2 + 1]);

        // ---- sub-batch 1: kt 2,3 ----
        #pragma unroll
        for (int kt = 0; kt < 2; kt++) {
            #pragma unroll
            for (int mt = 0; mt < 4; mt++)
                ldsm4(af[kt][mt], aS + mt * 16 * (ASTR * 2) + (kt + 2) * 32);
            #pragma unroll
            for (int ntp = 0; ntp < 3; ntp++)
                ldsm4t(bf[kt][ntp], bS + (kt + 2) * 16 * (BSTR * 2) + ntp * 32);
        }
        #pragma unroll
        for (int kt = 0; kt < 2; kt++)
            #pragma unroll
            for (int mt = 0; mt < 4; mt++)
                #pragma unroll
                for (int nt = 0; nt < 6; nt++)
                    mma16(acc[mt][nt], af[kt][mt],
                          bf[kt][nt >> 1][(nt & 1) * 2], bf[kt][nt >> 1][(nt & 1) * 2 + 1]);

        if (kb + 2 < NKB)      { CP_WAIT(1); }
        else if (kb + 1 < NKB) { CP_WAIT(0); }
        __syncthreads();
        if (++slot == NSTG) slot = 0;
    }

    // Epilogue: 96 | 192 so a CTA column never crosses a head boundary class
    #pragma unroll
    for (int nt = 0; nt < 6; nt++) {
        int n0 = bn * TN_G + wcol * 48 + nt * 8 + 2 * t;
        float bx = __ldg(&bias[n0]), by = __ldg(&bias[n0 + 1]);
        int h = n0 / 192;
        int r = n0 - h * 192;
        __half* dst = (r < 64) ? g_Qh : ((r < 128) ? g_Kh : g_Vh);
        float scl = (r < 64) ? 0.125f : 1.f;
        #pragma unroll
        for (int mt = 0; mt < 4; mt++) {
            #pragma unroll
            for (int half_ = 0; half_ < 2; half_++) {
                int m  = bm * 256 + wrow * 64 + mt * 16 + g + half_ * 8;
                int b_ = m >> 11;
                int s_ = m & 2047;
                size_t o = ((((size_t)b_ * NH + h) * SEQ) + s_) * HD + (r & 63);
                *(__half2*)(dst + o) = __floats2half2_rn((acc[mt][nt][half_ * 2]     + bx) * scl,
                                                         (acc[mt][nt][half_ * 2 + 1] + by) * scl);
            }
        }
    }
}

// ---------------------------------------------------------------------------
// Kernel 2: causal flash attention, fp16 mma + ldmatrix, register-resident P.
// CTAQ=128: 4 warps x 32 q-rows, 128 threads, 2 CTAs/SM co-resident.
// ---------------------------------------------------------------------------
#define QSTR 72
#define KSTR 72
#define KV_B (64*KSTR*2)
#define CTAQ 128
#define NTHR 128
#define L2E 1.44269504f

__global__ __launch_bounds__(NTHR, 2) void attn_fa(float* __restrict__ out)
{
    extern __shared__ __half smh[];
    __half* Qs = smh;
    __half* Ks = Qs + CTAQ * QSTR;
    __half* Vs = Ks + 2 * 64 * KSTR;
    const uint32_t uQ = smem_u32(Qs);
    const uint32_t uK = smem_u32(Ks);
    const uint32_t uV = smem_u32(Vs);

    const int tid  = threadIdx.x;
    const int wid  = tid >> 5;
    const int lane = tid & 31;
    const int g = lane >> 2, t = lane & 3;
    const int qt = gridDim.x - 1 - blockIdx.x;    // big-work CTAs first
    const int h = blockIdx.y, b = blockIdx.z;
    const int wb = wid * 32;
    const int qbase = qt * CTAQ;
    const int row0 = qbase + wb + g;

    const size_t hb = (((size_t)b * NH + h) * SEQ) * HD;
    const int nkb = (qt + 1) * (CTAQ / 64);

    // K/V: 512 chunks per tensor -> 4/thread; Q: 1024 chunks -> 8/thread
    int kvrow[4], kvcol[4];
    #pragma unroll
    for (int i = 0; i < 4; i++) {
        int idx = tid + i * NTHR;
        kvrow[i] = idx >> 3;
        kvcol[i] = (idx & 7) * 8;
    }
    auto issueKV = [&](int kb, int slot) {
        const __half* ks = g_Kh + hb + (size_t)kb * 64 * HD;
        const __half* vs = g_Vh + hb + (size_t)kb * 64 * HD;
        #pragma unroll
        for (int i = 0; i < 4; i++) {
            cp16(uK + slot * KV_B + (kvrow[i] * KSTR + kvcol[i]) * 2, ks + kvrow[i] * HD + kvcol[i]);
            cp16(uV + slot * KV_B + (kvrow[i] * KSTR + kvcol[i]) * 2, vs + kvrow[i] * HD + kvcol[i]);
        }
    };

    issueKV(0, 0);
    CP_COMMIT();
    {
        const __half* qs = g_Qh + hb + (size_t)qbase * HD;
        #pragma unroll
        for (int i = 0; i < 8; i++) {
            int idx = tid + i * NTHR;
            int r = idx >> 3, c = (idx & 7) * 8;
            cp16(uQ + (r * QSTR + c) * 2, qs + r * HD + c);
        }
    }
    CP_COMMIT();
    CP_WAIT(0);
    __syncthreads();

    uint32_t aq[2][4][4];
    {
        const uint32_t qb = uQ + (wb + (lane & 15)) * (QSTR * 2) + ((lane & 16) ? 16 : 0);
        #pragma unroll
        for (int mt = 0; mt < 2; mt++)
            #pragma unroll
            for (int kt = 0; kt < 4; kt++)
                ldsm4(aq[mt][kt], qb + mt * 16 * (QSTR * 2) + kt * 32);
    }

    float o[2][8][4];
    #pragma unroll
    for (int mt = 0; mt < 2; mt++)
        #pragma unroll
        for (int nt = 0; nt < 8; nt++)
            #pragma unroll
            for (int e = 0; e < 4; e++) o[mt][nt][e] = 0.f;
    float m00 = -1e30f, m01 = -1e30f, m10 = -1e30f, m11 = -1e30f;
    float l00 = 0.f, l01 = 0.f, l10 = 0.f, l11 = 0.f;

    const uint32_t kfOff = ((lane & 7) + ((lane & 16) ? 8 : 0)) * (KSTR * 2) + ((lane & 8) ? 16 : 0);
    const uint32_t vfOff = ((lane & 7) + ((lane & 8) ? 8 : 0)) * (KSTR * 2) + ((lane & 16) ? 16 : 0);

    #pragma unroll 1
    for (int kb = 0; kb < nkb; kb++) {
        const int slot = kb & 1;
        if (kb + 1 < nkb) { issueKV(kb + 1, slot ^ 1); CP_COMMIT(); }
        if (kb + 1 < nkb) { CP_WAIT(1); } else { CP_WAIT(0); }
        __syncthreads();

        if (kb * 64 <= qbase + wb + 31) {
            float s[2][8][4];
            #pragma unroll
            for (int mt = 0; mt < 2; mt++)
                #pragma unroll
                for (int nt = 0; nt < 8; nt++)
                    #pragma unroll
                    for (int e = 0; e < 4; e++) s[mt][nt][e] = 0.f;

            const uint32_t kbase_ = uK + slot * KV_B + kfOff;
            #pragma unroll
            for (int kt = 0; kt < 4; kt++) {
                uint32_t kf[4][4];
                #pragma unroll
                for (int ntp = 0; ntp < 4; ntp++)
                    ldsm4(kf[ntp], kbase_ + ntp * 16 * (KSTR * 2) + kt * 32);
                #pragma unroll
                for (int nt = 0; nt < 8; nt++) {
                    uint32_t b0 = kf[nt >> 1][(nt & 1) * 2], b1 = kf[nt >> 1][(nt & 1) * 2 + 1];
                    mma16(s[0][nt], aq[0][kt], b0, b1);
                    mma16(s[1][nt], aq[1][kt], b0, b1);
                }
            }

            if (kb * 64 + 63 > qbase + wb) {
                #pragma unroll
                for (int nt = 0; nt < 8; nt++) {
                    int col = kb * 64 + nt * 8 + 2 * t;
                    if (col     > row0)      s[0][nt][0] = -1e30f;
                    if (col + 1 > row0)      s[0][nt][1] = -1e30f;
                    if (col     > row0 + 8)  s[0][nt][2] = -1e30f;
                    if (col + 1 > row0 + 8)  s[0][nt][3] = -1e30f;
                    if (col     > row0 + 16) s[1][nt][0] = -1e30f;
                    if (col + 1 > row0 + 16) s[1][nt][1] = -1e30f;
                    if (col     > row0 + 24) s[1][nt][2] = -1e30f;
                    if (col + 1 > row0 + 24) s[1][nt][3] = -1e30f;
                }
            }

            float b00 = -1e30f, b01 = -1e30f, b10 = -1e30f, b11 = -1e30f;
            #pragma unroll
            for (int nt = 0; nt < 8; nt++) {
                b00 = fmaxf(b00, fmaxf(s[0][nt][0], s[0][nt][1]));
                b01 = fmaxf(b01, fmaxf(s[0][nt][2], s[0][nt][3]));
                b10 = fmaxf(b10, fmaxf(s[1][nt][0], s[1][nt][1]));
                b11 = fmaxf(b11, fmaxf(s[1][nt][2], s[1][nt][3]));
            }
            #pragma unroll
            for (int d = 1; d <= 2; d <<= 1) {
                b00 = fmaxf(b00, __shfl_xor_sync(0xffffffffu, b00, d));
                b01 = fmaxf(b01, __shfl_xor_sync(0xffffffffu, b01, d));
                b10 = fmaxf(b10, __shfl_xor_sync(0xffffffffu, b10, d));
                b11 = fmaxf(b11, __shfl_xor_sync(0xffffffffu, b11, d));
            }
            float n00 = fmaxf(m00, b00), n01 = fmaxf(m01, b01);
            float n10 = fmaxf(m10, b10), n11 = fmaxf(m11, b11);
            float c00 = exp2f((m00 - n00) * L2E), c01 = exp2f((m01 - n01) * L2E);
            float c10 = exp2f((m10 - n10) * L2E), c11 = exp2f((m11 - n11) * L2E);

            uint32_t pc[2][8][2];
            float s00 = 0.f, s01 = 0.f, s10 = 0.f, s11 = 0.f;
            #pragma unroll
            for (int nt = 0; nt < 8; nt++) {
                float p0 = exp2f((s[0][nt][0] - n00) * L2E);
                float p1 = exp2f((s[0][nt][1] - n00) * L2E);
                float p2 = exp2f((s[0][nt][2] - n01) * L2E);
                float p3 = exp2f((s[0][nt][3] - n01) * L2E);
                float q0 = exp2f((s[1][nt][0] - n10) * L2E);
                float q1 = exp2f((s[1][nt][1] - n10) * L2E);
                float q2 = exp2f((s[1][nt][2] - n11) * L2E);
                float q3 = exp2f((s[1][nt][3] - n11) * L2E);
                s00 += p0 + p1; s01 += p2 + p3;
                s10 += q0 + q1; s11 += q2 + q3;
                pc[0][nt][0] = pack2(p0, p1);
                pc[0][nt][1] = pack2(p2, p3);
                pc[1][nt][0] = pack2(q0, q1);
                pc[1][nt][1] = pack2(q2, q3);
            }
            #pragma unroll
            for (int d = 1; d <= 2; d <<= 1) {
                s00 += __shfl_xor_sync(0xffffffffu, s00, d);
                s01 += __shfl_xor_sync(0xffffffffu, s01, d);
                s10 += __shfl_xor_sync(0xffffffffu, s10, d);
                s11 += __shfl_xor_sync(0xffffffffu, s11, d);
            }
            l00 = l00 * c00 + s00; l01 = l01 * c01 + s01;
            l10 = l10 * c10 + s10; l11 = l11 * c11 + s11;
            m00 = n00; m01 = n01; m10 = n10; m11 = n11;

            #pragma unroll
            for (int nt = 0; nt < 8; nt++) {
                o[0][nt][0] *= c00; o[0][nt][1] *= c00;
                o[0][nt][2] *= c01; o[0][nt][3] *= c01;
                o[1][nt][0] *= c10; o[1][nt][1] *= c10;
                o[1][nt][2] *= c11; o[1][nt][3] *= c11;
            }

            const uint32_t vbase_ = uV + slot * KV_B + vfOff;
            #pragma unroll
            for (int kt = 0; kt < 4; kt++) {
                uint32_t vf[4][4];
                #pragma unroll
                for (int ntp = 0; ntp < 4; ntp++)
                    ldsm4t(vf[ntp], vbase_ + kt * 16 * (KSTR * 2) + ntp * 32);
                uint32_t ap0[4] = {pc[0][2*kt][0], pc[0][2*kt][1], pc[0][2*kt+1][0], pc[0][2*kt+1][1]};
                uint32_t ap1[4] = {pc[1][2*kt][0], pc[1][2*kt][1], pc[1][2*kt+1][0], pc[1][2*kt+1][1]};
                #pragma unroll
                for (int nt = 0; nt < 8; nt++) {
                    uint32_t b0 = vf[nt >> 1][(nt & 1) * 2], b1 = vf[nt >> 1][(nt & 1) * 2 + 1];
                    mma16(o[0][nt], ap0, b0, b1);
                    mma16(o[1][nt], ap1, b0, b1);
                }
            }
        }

        __syncthreads();
    }

    const float i00 = 1.f / l00, i01 = 1.f / l01;
    const float i10 = 1.f / l10, i11 = 1.f / l11;
    float* w00 = out + ((size_t)b * SEQ + row0) * DM + h * HD + 2 * t;
    float* w01 = out + ((size_t)b * SEQ + row0 + 8) * DM + h * HD + 2 * t;
    float* w10 = out + ((size_t)b * SEQ + row0 + 16) * DM + h * HD + 2 * t;
    float* w11 = out + ((size_t)b * SEQ + row0 + 24) * DM + h * HD + 2 * t;
    #pragma unroll
    for (int nt = 0; nt < 8; nt++) {
        *(float2*)(w00 + nt * 8) = make_float2(o[0][nt][0] * i00, o[0][nt][1] * i00);
        *(float2*)(w01 + nt * 8) = make_float2(o[0][nt][2] * i01, o[0][nt][3] * i01);
        *(float2*)(w10 + nt * 8) = make_float2(o[1][nt][0] * i10, o[1][nt][1] * i10);
        *(float2*)(w11 + nt * 8) = make_float2(o[1][nt][2] * i11, o[1][nt][3] * i11);
    }
}

// ---------------------------------------------------------------------------
extern "C" void kernel_launch(void* const* d_in, const int* in_sizes, int n_in,
                              void* d_out, int out_size)
{
    (void)in_sizes; (void)n_in; (void)out_size;
    const float* x    = (const float*)d_in[0];
    const float* Wqkv = (const float*)d_in[1];
    const float* bqkv = (const float*)d_in[2];
    float* out = (float*)d_out;

    cvt_all<<<888, 256>>>(x, Wqkv);

    const int gemm_smem = NSTG * (SA_B + SB_B);              // 150528 B
    cudaFuncSetAttribute(qkv_gemm, cudaFuncAttributeMaxDynamicSharedMemorySize, gemm_smem);
    dim3 ggrid(N_TOT / TN_G, M_TOT / 256);                   // (32, 32) = 1024 CTAs
    qkv_gemm<<<ggrid, 256, gemm_smem>>>(bqkv);

    const int attn_smem = (CTAQ * QSTR + 4 * 64 * KSTR) * 2; // 55296 B (2 CTAs/SM)
    cudaFuncSetAttribute(attn_fa, cudaFuncAttributeMaxDynamicSharedMemorySize, attn_smem);
    dim3 agrid(SEQ / CTAQ, NH, BZ);                          // (16, 16, 4) = 1024
    attn_fa<<<agrid, NTHR, attn_smem>>>(out);
}

// round 14
// speedup vs baseline: 1.2682x; 1.0189x over previous
#include <cuda_runtime.h>
#include <cuda_fp16.h>
#include <cstdint>

// Problem constants
#define BZ 4
#define SEQ 2048
#define DM 1024
#define NH 16
#define HD 64
#define M_TOT 8192
#define N_TOT 3072

// Scratch (fp16)
__device__ __half g_Qh[BZ*NH*SEQ*HD];
__device__ __half g_Kh[BZ*NH*SEQ*HD];
__device__ __half g_Vh[BZ*NH*SEQ*HD];
__device__ __half g_Xh[M_TOT*DM];
__device__ __half g_Wh[(size_t)DM*N_TOT];   // W fp16, NATIVE [k][n] layout

// ---------------------------------------------------------------------------
// helpers
// ---------------------------------------------------------------------------
__device__ __forceinline__ void mma16(float* c, const uint32_t* a, uint32_t b0, uint32_t b1){
    asm volatile("mma.sync.aligned.m16n8k16.row.col.f32.f16.f16.f32 "
        "{%0,%1,%2,%3}, {%4,%5,%6,%7}, {%8,%9}, {%0,%1,%2,%3};"
        : "+f"(c[0]), "+f"(c[1]), "+f"(c[2]), "+f"(c[3])
        : "r"(a[0]), "r"(a[1]), "r"(a[2]), "r"(a[3]), "r"(b0), "r"(b1));
}
__device__ __forceinline__ void ldsm4(uint32_t* r, uint32_t addr){
    asm volatile("ldmatrix.sync.aligned.m8n8.x4.shared.b16 {%0,%1,%2,%3}, [%4];"
        : "=r"(r[0]), "=r"(r[1]), "=r"(r[2]), "=r"(r[3]) : "r"(addr));
}
__device__ __forceinline__ void ldsm4t(uint32_t* r, uint32_t addr){
    asm volatile("ldmatrix.sync.aligned.m8n8.x4.trans.shared.b16 {%0,%1,%2,%3}, [%4];"
        : "=r"(r[0]), "=r"(r[1]), "=r"(r[2]), "=r"(r[3]) : "r"(addr));
}
__device__ __forceinline__ uint32_t pack2(float lo, float hi){
    uint32_t r; asm("cvt.rn.f16x2.f32 %0, %1, %2;" : "=r"(r) : "f"(hi), "f"(lo)); return r;
}
__device__ __forceinline__ uint32_t smem_u32(const void* p){
    uint32_t a;
    asm("{ .reg .u64 t; cvta.to.shared.u64 t, %1; cvt.u32.u64 %0, t; }" : "=r"(a) : "l"(p));
    return a;
}
__device__ __forceinline__ void cp16(uint32_t dst, const void* src){
    asm volatile("cp.async.cg.shared.global [%0], [%1], 16;" :: "r"(dst), "l"(src));
}
#define CP_COMMIT() asm volatile("cp.async.commit_group;" ::: "memory")
#define CP_WAIT(n)  asm volatile("cp.async.wait_group %0;" :: "n"(n) : "memory")

// ---------------------------------------------------------------------------
// Prepass: fused elementwise fp32 -> fp16 for x and W (single index space).
// ---------------------------------------------------------------------------
__global__ __launch_bounds__(256) void cvt_all(const float* __restrict__ x,
                                               const float* __restrict__ W)
{
    const size_t NX = (size_t)M_TOT * DM / 4;
    const size_t NT = NX + (size_t)DM * N_TOT / 4;
    const size_t gid = (size_t)blockIdx.x * blockDim.x + threadIdx.x;
    const size_t stride = (size_t)gridDim.x * blockDim.x;
    for (size_t i = gid; i < NT; i += stride) {
        if (i < NX) {
            float4 v = ((const float4*)x)[i];
            __half2* o = (__half2*)(g_Xh + i * 4);
            o[0] = __floats2half2_rn(v.x, v.y);
            o[1] = __floats2half2_rn(v.z, v.w);
        } else {
            size_t j = i - NX;
            float4 v = ((const float4*)W)[j];
            __half2* o = (__half2*)(g_Wh + j * 4);
            o[0] = __floats2half2_rn(v.x, v.y);
            o[1] = __floats2half2_rn(v.z, v.w);
        }
    }
}

// ---------------------------------------------------------------------------
// Kernel 1: QKV GEMM, fp16 mma, BK=64, 3-stage cp.async. (unchanged: at floor)
// CTA tile 256x96, 8 warps (4M x 2N), warp tile 64x48. B [k][n] via ldsm4t.
// ---------------------------------------------------------------------------
#define ASTR 72
#define BSTR 104
#define TN_G 96
#define SA_H (256*ASTR)
#define SB_H (64*BSTR)
#define SA_B (SA_H*2)
#define SB_B (SB_H*2)
#define NKB  (DM/64)
#define NSTG 3

__global__ __launch_bounds__(256, 1) void qkv_gemm(const float* __restrict__ bias)
{
    extern __shared__ __half smh[];
    __half* sA = smh;
    __half* sB = smh + NSTG * SA_H;
    const uint32_t uA = smem_u32(sA);
    const uint32_t uB = smem_u32(sB);

    const int tid  = threadIdx.x;
    const int wid  = tid >> 5;
    const int lane = tid & 31;
    const int g = lane >> 2, t = lane & 3;
    const int wrow = wid & 3;
    const int wcol = wid >> 2;
    const int bm = blockIdx.y, bn = blockIdx.x;

    const __half* Ab = g_Xh + (size_t)(bm * 256) * DM;
    const __half* Bb = g_Wh + (size_t)bn * TN_G;

    int arow[8], acol[8];
    #pragma unroll
    for (int l = 0; l < 8; l++) {
        int idx = tid + l * 256;
        arow[l] = idx >> 3;
        acol[l] = (idx & 7) * 8;
    }
    int brow[3], bcol[3];
    #pragma unroll
    for (int l = 0; l < 3; l++) {
        int idx = tid + l * 256;
        brow[l] = idx / 12;
        bcol[l] = (idx % 12) * 8;
    }

    auto issue = [&](int slot, int k0) {
        uint32_t pa = uA + slot * SA_B;
        uint32_t pb = uB + slot * SB_B;
        #pragma unroll
        for (int l = 0; l < 8; l++)
            cp16(pa + (arow[l] * ASTR + acol[l]) * 2, Ab + (size_t)arow[l] * DM + k0 + acol[l]);
        #pragma unroll
        for (int l = 0; l < 3; l++)
            cp16(pb + (brow[l] * BSTR + bcol[l]) * 2, Bb + (size_t)(k0 + brow[l]) * N_TOT + bcol[l]);
    };

    float acc[4][6][4];
    #pragma unroll
    for (int mt = 0; mt < 4; mt++)
        #pragma unroll
        for (int nt = 0; nt < 6; nt++)
            #pragma unroll
            for (int e = 0; e < 4; e++) acc[mt][nt][e] = 0.f;

    issue(0, 0);   CP_COMMIT();
    issue(1, 64);  CP_COMMIT();
    CP_WAIT(1);
    __syncthreads();

    const uint32_t aBase = uA + (wrow * 64 + (lane & 15)) * (ASTR * 2) + ((lane & 16) ? 16 : 0);
    const uint32_t bBase = uB + ((lane & 7) + ((lane & 8) ? 8 : 0)) * (BSTR * 2)
                         + ((lane & 16) ? 16 : 0) + wcol * 48 * 2;

    int slot = 0;
    #pragma unroll 1
    for (int kb = 0; kb < NKB; kb++) {
        const uint32_t aS = aBase + slot * SA_B;
        const uint32_t bS = bBase + slot * SB_B;

        uint32_t af[2][4][4], bf[2][3][4];
        #pragma unroll
        for (int kt = 0; kt < 2; kt++) {
            #pragma unroll
            for (int mt = 0; mt < 4; mt++)
                ldsm4(af[kt][mt], aS + mt * 16 * (ASTR * 2) + kt * 32);
            #pragma unroll
            for (int ntp = 0; ntp < 3; ntp++)
                ldsm4t(bf[kt][ntp], bS + kt * 16 * (BSTR * 2) + ntp * 32);
        }

        if (kb + 2 < NKB) {
            int ns = slot + 2; if (ns >= NSTG) ns -= NSTG;
            issue(ns, (kb + 2) * 64);
            CP_COMMIT();
        }

        #pragma unroll
        for (int kt = 0; kt < 2; kt++)
            #pragma unroll
            for (int mt = 0; mt < 4; mt++)
                #pragma unroll
                for (int nt = 0; nt < 6; nt++)
                    mma16(acc[mt][nt], af[kt][mt],
                          bf[kt][nt >> 1][(nt & 1) * 2], bf[kt][nt >> 1][(nt & 1) * 2 + 1]);

        #pragma unroll
        for (int kt = 0; kt < 2; kt++) {
            #pragma unroll
            for (int mt = 0; mt < 4; mt++)
                ldsm4(af[kt][mt], aS + mt * 16 * (ASTR * 2) + (kt + 2) * 32);
            #pragma unroll
            for (int ntp = 0; ntp < 3; ntp++)
                ldsm4t(bf[kt][ntp], bS + (kt + 2) * 16 * (BSTR * 2) + ntp * 32);
        }
        #pragma unroll
        for (int kt = 0; kt < 2; kt++)
            #pragma unroll
            for (int mt = 0; mt < 4; mt++)
                #pragma unroll
                for (int nt = 0; nt < 6; nt++)
                    mma16(acc[mt][nt], af[kt][mt],
                          bf[kt][nt >> 1][(nt & 1) * 2], bf[kt][nt >> 1][(nt & 1) * 2 + 1]);

        if (kb + 2 < NKB)      { CP_WAIT(1); }
        else if (kb + 1 < NKB) { CP_WAIT(0); }
        __syncthreads();
        if (++slot == NSTG) slot = 0;
    }

    #pragma unroll
    for (int nt = 0; nt < 6; nt++) {
        int n0 = bn * TN_G + wcol * 48 + nt * 8 + 2 * t;
        float bx = __ldg(&bias[n0]), by = __ldg(&bias[n0 + 1]);
        int h = n0 / 192;
        int r = n0 - h * 192;
        __half* dst = (r < 64) ? g_Qh : ((r < 128) ? g_Kh : g_Vh);
        float scl = (r < 64) ? 0.125f : 1.f;
        #pragma unroll
        for (int mt = 0; mt < 4; mt++) {
            #pragma unroll
            for (int half_ = 0; half_ < 2; half_++) {
                int m  = bm * 256 + wrow * 64 + mt * 16 + g + half_ * 8;
                int b_ = m >> 11;
                int s_ = m & 2047;
                size_t o = ((((size_t)b_ * NH + h) * SEQ) + s_) * HD + (r & 63);
                *(__half2*)(dst + o) = __floats2half2_rn((acc[mt][nt][half_ * 2]     + bx) * scl,
                                                         (acc[mt][nt][half_ * 2 + 1] + by) * scl);
            }
        }
    }
}

// ---------------------------------------------------------------------------
// Kernel 2: causal flash attention, fp16 mma + ldmatrix, register-resident P.
// CTAQ=128: 4 warps x 32 q-rows, 128 threads, 2 CTAs/SM.
// Single-sync pipelined KV loop: WAIT -> sync -> issue(next) -> compute.
// ---------------------------------------------------------------------------
#define QSTR 72
#define KSTR 72
#define KV_B (64*KSTR*2)
#define CTAQ 128
#define NTHR 128
#define L2E 1.44269504f

__global__ __launch_bounds__(NTHR, 2) void attn_fa(float* __restrict__ out)
{
    extern __shared__ __half smh[];
    __half* Qs = smh;
    __half* Ks = Qs + CTAQ * QSTR;
    __half* Vs = Ks + 2 * 64 * KSTR;
    const uint32_t uQ = smem_u32(Qs);
    const uint32_t uK = smem_u32(Ks);
    const uint32_t uV = smem_u32(Vs);

    const int tid  = threadIdx.x;
    const int wid  = tid >> 5;
    const int lane = tid & 31;
    const int g = lane >> 2, t = lane & 3;
    const int qt = gridDim.x - 1 - blockIdx.x;    // big-work CTAs first
    const int h = blockIdx.y, b = blockIdx.z;
    const int wb = wid * 32;
    const int qbase = qt * CTAQ;
    const int row0 = qbase + wb + g;

    const size_t hb = (((size_t)b * NH + h) * SEQ) * HD;
    const int nkb = (qt + 1) * (CTAQ / 64);

    int kvrow[4], kvcol[4];
    #pragma unroll
    for (int i = 0; i < 4; i++) {
        int idx = tid + i * NTHR;
        kvrow[i] = idx >> 3;
        kvcol[i] = (idx & 7) * 8;
    }
    auto issueKV = [&](int kb, int slot) {
        const __half* ks = g_Kh + hb + (size_t)kb * 64 * HD;
        const __half* vs = g_Vh + hb + (size_t)kb * 64 * HD;
        #pragma unroll
        for (int i = 0; i < 4; i++) {
            cp16(uK + slot * KV_B + (kvrow[i] * KSTR + kvcol[i]) * 2, ks + kvrow[i] * HD + kvcol[i]);
            cp16(uV + slot * KV_B + (kvrow[i] * KSTR + kvcol[i]) * 2, vs + kvrow[i] * HD + kvcol[i]);
        }
    };

    // Prologue: Q tile + first KV tile in one group.
    {
        const __half* qs = g_Qh + hb + (size_t)qbase * HD;
        #pragma unroll
        for (int i = 0; i < 8; i++) {
            int idx = tid + i * NTHR;
            int r = idx >> 3, c = (idx & 7) * 8;
            cp16(uQ + (r * QSTR + c) * 2, qs + r * HD + c);
        }
    }
    issueKV(0, 0);
    CP_COMMIT();
    CP_WAIT(0);
    __syncthreads();

    uint32_t aq[2][4][4];
    {
        const uint32_t qb = uQ + (wb + (lane & 15)) * (QSTR * 2) + ((lane & 16) ? 16 : 0);
        #pragma unroll
        for (int mt = 0; mt < 2; mt++)
            #pragma unroll
            for (int kt = 0; kt < 4; kt++)
                ldsm4(aq[mt][kt], qb + mt * 16 * (QSTR * 2) + kt * 32);
    }

    float o[2][8][4];
    #pragma unroll
    for (int mt = 0; mt < 2; mt++)
        #pragma unroll
        for (int nt = 0; nt < 8; nt++)
            #pragma unroll
            for (int e = 0; e < 4; e++) o[mt][nt][e] = 0.f;
    float m00 = -1e30f, m01 = -1e30f, m10 = -1e30f, m11 = -1e30f;
    float l00 = 0.f, l01 = 0.f, l10 = 0.f, l11 = 0.f;

    const uint32_t kfOff = ((lane & 7) + ((lane & 16) ? 8 : 0)) * (KSTR * 2) + ((lane & 8) ? 16 : 0);
    const uint32_t vfOff = ((lane & 7) + ((lane & 8) ? 8 : 0)) * (KSTR * 2) + ((lane & 16) ? 16 : 0);

    #pragma unroll 1
    for (int kb = 0; kb < nkb; kb++) {
        const int slot = kb & 1;
        // slot data is complete and visible here.
        // (kb==0: prologue wait+sync. kb>0: end-of-previous-iter wait+sync.)

        // Issue next tile into slot^1 — safe: all reads of slot^1 (previous
        // iteration's compute) completed before the barrier we just passed.
        if (kb + 1 < nkb) { issueKV(kb + 1, slot ^ 1); CP_COMMIT(); }

        if (kb * 64 <= qbase + wb + 31) {
            float s[2][8][4];
            #pragma unroll
            for (int mt = 0; mt < 2; mt++)
                #pragma unroll
                for (int nt = 0; nt < 8; nt++)
                    #pragma unroll
                    for (int e = 0; e < 4; e++) s[mt][nt][e] = 0.f;

            const uint32_t kbase_ = uK + slot * KV_B + kfOff;
            #pragma unroll
            for (int kt = 0; kt < 4; kt++) {
                uint32_t kf[4][4];
                #pragma unroll
                for (int ntp = 0; ntp < 4; ntp++)
                    ldsm4(kf[ntp], kbase_ + ntp * 16 * (KSTR * 2) + kt * 32);
                #pragma unroll
                for (int nt = 0; nt < 8; nt++) {
                    uint32_t b0 = kf[nt >> 1][(nt & 1) * 2], b1 = kf[nt >> 1][(nt & 1) * 2 + 1];
                    mma16(s[0][nt], aq[0][kt], b0, b1);
                    mma16(s[1][nt], aq[1][kt], b0, b1);
                }
            }

            if (kb * 64 + 63 > qbase + wb) {
                #pragma unroll
                for (int nt = 0; nt < 8; nt++) {
                    int col = kb * 64 + nt * 8 + 2 * t;
                    if (col     > row0)      s[0][nt][0] = -1e30f;
                    if (col + 1 > row0)      s[0][nt][1] = -1e30f;
                    if (col     > row0 + 8)  s[0][nt][2] = -1e30f;
                    if (col + 1 > row0 + 8)  s[0][nt][3] = -1e30f;
                    if (col     > row0 + 16) s[1][nt][0] = -1e30f;
                    if (col + 1 > row0 + 16) s[1][nt][1] = -1e30f;
                    if (col     > row0 + 24) s[1][nt][2] = -1e30f;
                    if (col + 1 > row0 + 24) s[1][nt][3] = -1e30f;
                }
            }

            float b00 = -1e30f, b01 = -1e30f, b10 = -1e30f, b11 = -1e30f;
            #pragma unroll
            for (int nt = 0; nt < 8; nt++) {
                b00 = fmaxf(b00, fmaxf(s[0][nt][0], s[0][nt][1]));
                b01 = fmaxf(b01, fmaxf(s[0][nt][2], s[0][nt][3]));
                b10 = fmaxf(b10, fmaxf(s[1][nt][0], s[1][nt][1]));
                b11 = fmaxf(b11, fmaxf(s[1][nt][2], s[1][nt][3]));
            }
            #pragma unroll
            for (int d = 1; d <= 2; d <<= 1) {
                b00 = fmaxf(b00, __shfl_xor_sync(0xffffffffu, b00, d));
                b01 = fmaxf(b01, __shfl_xor_sync(0xffffffffu, b01, d));
                b10 = fmaxf(b10, __shfl_xor_sync(0xffffffffu, b10, d));
                b11 = fmaxf(b11, __shfl_xor_sync(0xffffffffu, b11, d));
            }
            float n00 = fmaxf(m00, b00), n01 = fmaxf(m01, b01);
            float n10 = fmaxf(m10, b10), n11 = fmaxf(m11, b11);
            float c00 = exp2f((m00 - n00) * L2E), c01 = exp2f((m01 - n01) * L2E);
            float c10 = exp2f((m10 - n10) * L2E), c11 = exp2f((m11 - n11) * L2E);

            uint32_t pc[2][8][2];
            float s00 = 0.f, s01 = 0.f, s10 = 0.f, s11 = 0.f;
            #pragma unroll
            for (int nt = 0; nt < 8; nt++) {
                float p0 = exp2f((s[0][nt][0] - n00) * L2E);
                float p1 = exp2f((s[0][nt][1] - n00) * L2E);
                float p2 = exp2f((s[0][nt][2] - n01) * L2E);
                float p3 = exp2f((s[0][nt][3] - n01) * L2E);
                float q0 = exp2f((s[1][nt][0] - n10) * L2E);
                float q1 = exp2f((s[1][nt][1] - n10) * L2E);
                float q2 = exp2f((s[1][nt][2] - n11) * L2E);
                float q3 = exp2f((s[1][nt][3] - n11) * L2E);
                s00 += p0 + p1; s01 += p2 + p3;
                s10 += q0 + q1; s11 += q2 + q3;
                pc[0][nt][0] = pack2(p0, p1);
                pc[0][nt][1] = pack2(p2, p3);
                pc[1][nt][0] = pack2(q0, q1);
                pc[1][nt][1] = pack2(q2, q3);
            }
            #pragma unroll
            for (int d = 1; d <= 2; d <<= 1) {
                s00 += __shfl_xor_sync(0xffffffffu, s00, d);
                s01 += __shfl_xor_sync(0xffffffffu, s01, d);
                s10 += __shfl_xor_sync(0xffffffffu, s10, d);
                s11 += __shfl_xor_sync(0xffffffffu, s11, d);
            }
            l00 = l00 * c00 + s00; l01 = l01 * c01 + s01;
            l10 = l10 * c10 + s10; l11 = l11 * c11 + s11;
            m00 = n00; m01 = n01; m10 = n10; m11 = n11;

            #pragma unroll
            for (int nt = 0; nt < 8; nt++) {
                o[0][nt][0] *= c00; o[0][nt][1] *= c00;
                o[0][nt][2] *= c01; o[0][nt][3] *= c01;
                o[1][nt][0] *= c10; o[1][nt][1] *= c10;
                o[1][nt][2] *= c11; o[1][nt][3] *= c11;
            }

            const uint32_t vbase_ = uV + slot * KV_B + vfOff;
            #pragma unroll
            for (int kt = 0; kt < 4; kt++) {
                uint32_t vf[4][4];
                #pragma unroll
                for (int ntp = 0; ntp < 4; ntp++)
                    ldsm4t(vf[ntp], vbase_ + kt * 16 * (KSTR * 2) + ntp * 32);
                uint32_t ap0[4] = {pc[0][2*kt][0], pc[0][2*kt][1], pc[0][2*kt+1][0], pc[0][2*kt+1][1]};
                uint32_t ap1[4] = {pc[1][2*kt][0], pc[1][2*kt][1], pc[1][2*kt+1][0], pc[1][2*kt+1][1]};
                #pragma unroll
                for (int nt = 0; nt < 8; nt++) {
                    uint32_t b0 = vf[nt >> 1][(nt & 1) * 2], b1 = vf[nt >> 1][(nt & 1) * 2 + 1];
                    mma16(o[0][nt], ap0, b0, b1);
                    mma16(o[1][nt], ap1, b0, b1);
                }
            }
        }

        // End of iteration: wait for next slot's data, then one barrier that
        // simultaneously (a) makes it visible to all warps, (b) certifies all
        // warps finished reading the current slot.
        if (kb + 1 < nkb) {
            CP_WAIT(0);
            __syncthreads();
        }
    }

    const float i00 = 1.f / l00, i01 = 1.f / l01;
    const float i10 = 1.f / l10, i11 = 1.f / l11;
    float* w00 = out + ((size_t)b * SEQ + row0) * DM + h * HD + 2 * t;
    float* w01 = out + ((size_t)b * SEQ + row0 + 8) * DM + h * HD + 2 * t;
    float* w10 = out + ((size_t)b * SEQ + row0 + 16) * DM + h * HD + 2 * t;
    float* w11 = out + ((size_t)b * SEQ + row0 + 24) * DM + h * HD + 2 * t;
    #pragma unroll
    for (int nt = 0; nt < 8; nt++) {
        *(float2*)(w00 + nt * 8) = make_float2(o[0][nt][0] * i00, o[0][nt][1] * i00);
        *(float2*)(w01 + nt * 8) = make_float2(o[0][nt][2] * i01, o[0][nt][3] * i01);
        *(float2*)(w10 + nt * 8) = make_float2(o[1][nt][0] * i10, o[1][nt][1] * i10);
        *(float2*)(w11 + nt * 8) = make_float2(o[1][nt][2] * i11, o[1][nt][3] * i11);
    }
}

// ---------------------------------------------------------------------------
extern "C" void kernel_launch(void* const* d_in, const int* in_sizes, int n_in,
                              void* d_out, int out_size)
{
    (void)in_sizes; (void)n_in; (void)out_size;
    const float* x    = (const float*)d_in[0];
    const float* Wqkv = (const float*)d_in[1];
    const float* bqkv = (const float*)d_in[2];
    float* out = (float*)d_out;

    cvt_all<<<1184, 256>>>(x, Wqkv);

    const int gemm_smem = NSTG * (SA_B + SB_B);              // 150528 B
    cudaFuncSetAttribute(qkv_gemm, cudaFuncAttributeMaxDynamicSharedMemorySize, gemm_smem);
    dim3 ggrid(N_TOT / TN_G, M_TOT / 256);                   // (32, 32) = 1024 CTAs
    qkv_gemm<<<ggrid, 256, gemm_smem>>>(bqkv);

    const int attn_smem = (CTAQ * QSTR + 4 * 64 * KSTR) * 2; // 55296 B (2 CTAs/SM)
    cudaFuncSetAttribute(attn_fa, cudaFuncAttributeMaxDynamicSharedMemorySize, attn_smem);
    dim3 agrid(SEQ / CTAQ, NH, BZ);                          // (16, 16, 4) = 1024
    attn_fa<<<agrid, NTHR, attn_smem>>>(out);
}